// round 3
// baseline (speedup 1.0000x reference)
#include <cuda_runtime.h>
#include <math.h>
#include <stdint.h>

// ---------------- problem constants ----------------
#define BATCH 2
#define T_    64
#define H_    32
#define W_    32
#define C_    192
#define L_    (T_*H_*W_)        // 65536 tokens per image
#define ROWS  (BATCH*L_)        // 131072 total rows
#define NH_   6
#define HD_   32
#define NTOK  128               // tokens per window
#define NWIN  512               // windows per image
#define C3    576               // 3*C
#define CM_   768               // mlp hidden
#define SCALE_ 0.17677669529663687f   // 32^-0.5

// ---------------- scratch (static device globals; no allocation) ----------------
__device__ float g_buf1[(size_t)ROWS * C_];    // h_win -> attn_out -> ln2_out
__device__ float g_buf2[(size_t)ROWS * CM_];   // qkv (576 cols used) -> mlp hidden
__device__ float g_x2  [(size_t)ROWS * C_];    // x after attention residual

// map a window row (win,n) -> linear source/dest position in the (B,T,H,W) image,
// accounting for the cyclic shift (-4,-2,-2). Same map serves partition (gather)
// and reverse (scatter) because roll(+s) inverts roll(-s).
__device__ __forceinline__ size_t shifted_pos(int row) {
    int win = row >> 7, n = row & 127;
    int b  = win >> 9, widx = win & 511;
    int tb = widx >> 6, hb = (widx >> 3) & 7, wb = widx & 7;
    int ti = n >> 4,   hi = (n >> 2) & 3,    wi = n & 3;
    int t  = (tb*8 + ti + 4) & 63;
    int hh = (hb*4 + hi + 2) & 31;
    int ww = (wb*4 + wi + 2) & 31;
    return (size_t)b * L_ + (size_t)t * (H_*W_) + hh * W_ + ww;
}

// ---------------- layernorm (optionally fused with shift+window-partition gather) ----------------
template<bool SHIFTMAP>
__global__ void k_ln(const float* __restrict__ x, const float* __restrict__ g,
                     const float* __restrict__ bt, float* __restrict__ out) {
    int r = blockIdx.x;          // destination row
    int c = threadIdx.x;         // 0..191
    size_t src = SHIFTMAP ? shifted_pos(r) * C_ : (size_t)r * C_;
    float v = x[src + c];
    float s1 = v, s2 = v * v;
    #pragma unroll
    for (int off = 16; off; off >>= 1) {
        s1 += __shfl_down_sync(0xffffffffu, s1, off);
        s2 += __shfl_down_sync(0xffffffffu, s2, off);
    }
    __shared__ float red[12];
    int warp = c >> 5, lane = c & 31;
    if (lane == 0) { red[warp] = s1; red[6 + warp] = s2; }
    __syncthreads();
    if (c == 0) {
        float a = 0.f, bb = 0.f;
        #pragma unroll
        for (int w2 = 0; w2 < 6; w2++) { a += red[w2]; bb += red[6 + w2]; }
        red[0] = a; red[6] = bb;
    }
    __syncthreads();
    float mu   = red[0] * (1.0f / 192.0f);
    float var  = red[6] * (1.0f / 192.0f) - mu * mu;
    float rstd = rsqrtf(var + 1e-5f);
    out[(size_t)r * C_ + c] = (v - mu) * rstd * g[c] + bt[c];
}

// ---------------- tiled fp32 GEMM, 64x64 tile, 256 threads, 4x4 microtile ----------------
// MODE 0: C = A*B + bias                       (qkv)
// MODE 1: scatter: x2[pos] = x[pos] + A*B+bias (proj + window-reverse + roll + residual)
// MODE 2: C = gelu_exact(A*B + bias)           (fc1)
// MODE 3: C = res + A*B + bias                 (fc2 + final residual)
template<int MODE>
__global__ void k_gemm(const float* __restrict__ A, const float* __restrict__ Bm,
                       const float* __restrict__ bias, float* __restrict__ Cm,
                       int M, int N, int K, const float* __restrict__ res) {
    __shared__ float As[16][68];
    __shared__ float Bs[16][68];
    int bm = blockIdx.y * 64, bn = blockIdx.x * 64;
    int tid  = threadIdx.x;
    int arow = tid >> 2,  acol = (tid & 3) * 4;   // A tile: 64 rows x 16 k
    int brow = tid >> 4,  bcol = (tid & 15) * 4;  // B tile: 16 k x 64 cols
    int ty   = tid >> 4,  tx   = tid & 15;
    float acc[4][4] = {};

    for (int k0 = 0; k0 < K; k0 += 16) {
        float4 av = *(const float4*)(A + (size_t)(bm + arow) * K + k0 + acol);
        As[acol + 0][arow] = av.x; As[acol + 1][arow] = av.y;
        As[acol + 2][arow] = av.z; As[acol + 3][arow] = av.w;
        float4 bv = *(const float4*)(Bm + (size_t)(k0 + brow) * N + bn + bcol);
        *(float4*)&Bs[brow][bcol] = bv;
        __syncthreads();
        #pragma unroll
        for (int kk = 0; kk < 16; kk++) {
            float4 a4 = *(const float4*)&As[kk][ty * 4];
            float4 b4 = *(const float4*)&Bs[kk][tx * 4];
            float ar[4] = {a4.x, a4.y, a4.z, a4.w};
            float br[4] = {b4.x, b4.y, b4.z, b4.w};
            #pragma unroll
            for (int u = 0; u < 4; u++)
                #pragma unroll
                for (int v = 0; v < 4; v++)
                    acc[u][v] += ar[u] * br[v];
        }
        __syncthreads();
    }

    #pragma unroll
    for (int u = 0; u < 4; u++) {
        int row = bm + ty * 4 + u;
        size_t dstbase;
        if (MODE == 1) dstbase = shifted_pos(row) * (size_t)N;
        else           dstbase = (size_t)row * N;
        #pragma unroll
        for (int v = 0; v < 4; v++) {
            int col = bn + tx * 4 + v;
            float val = acc[u][v] + bias[col];
            if (MODE == 0) {
                Cm[dstbase + col] = val;
            } else if (MODE == 1) {
                Cm[dstbase + col] = res[dstbase + col] + val;
            } else if (MODE == 2) {
                Cm[dstbase + col] = 0.5f * val * (1.0f + erff(val * 0.70710678118654752f));
            } else {
                Cm[dstbase + col] = res[dstbase + col] + val;
            }
        }
    }
}

// ---------------- fused window attention: one block per (window, head) ----------------
// Online (flash-style) softmax -> static shared memory only (~35 KB), no attribute call.
// qkv layout: row-major (win*128+n, 576); q cols [h*32..], k cols [192+h*32..], v cols [384+h*32..]
__global__ void k_attn(const float* __restrict__ qkv,
                       const float* __restrict__ rpb_table,
                       float* __restrict__ out) {
    __shared__ float kbuf[NTOK * HD_];   // 16 KB
    __shared__ float vbuf[NTOK * HD_];   // 16 KB
    __shared__ float rpbh[736];          // rpb slice for this head
    __shared__ int   labels[NTOK];

    int blk  = blockIdx.x;
    int win  = blk / NH_, head = blk % NH_;
    int i    = threadIdx.x;           // query row 0..127
    size_t base = (size_t)win * NTOK * C3 + head * HD_;

    // cooperative coalesced K/V stage (8 threads x float4 per row)
    {
        int d4 = (i & 7) * 4;
        for (int j = i >> 3; j < NTOK; j += 16) {
            const float* p = qkv + base + (size_t)j * C3;
            *(float4*)&kbuf[j * 32 + d4] = *(const float4*)(p + 192 + d4);
            *(float4*)&vbuf[j * 32 + d4] = *(const float4*)(p + 384 + d4);
        }
    }
    // relative-position-bias slice for this head
    for (int t = i; t < 735; t += NTOK) rpbh[t] = rpb_table[t * NH_ + head];

    // per-token shift-mask label (regions of the UNSHIFTED label image at shifted coords)
    int widx = win & 511;
    int tb = widx >> 6, hb = (widx >> 3) & 7, wb = widx & 7;
    int ti = i >> 4, hi = (i >> 2) & 3, wi = i & 3;
    {
        int gt = tb * 8 + ti, gh = hb * 4 + hi, gw = wb * 4 + wi;
        int rt = (gt < 56) ? 0 : (gt < 60 ? 1 : 2);
        int rh = (gh < 28) ? 0 : (gh < 30 ? 1 : 2);
        int rw = (gw < 28) ? 0 : (gw < 30 ? 1 : 2);
        labels[i] = rt * 9 + rh * 3 + rw;
    }
    __syncthreads();

    // load+scale my q row
    float qr[32];
    {
        const float* qp = qkv + base + (size_t)i * C3;
        #pragma unroll
        for (int d = 0; d < 32; d += 4) {
            float4 t4 = *(const float4*)(qp + d);
            qr[d] = t4.x * SCALE_; qr[d+1] = t4.y * SCALE_;
            qr[d+2] = t4.z * SCALE_; qr[d+3] = t4.w * SCALE_;
        }
    }
    int li  = labels[i];
    int dti = ti + 7, dhi = hi + 3, dwi = wi + 3;

    // online softmax over keys: running max m, running sum, rescaled PV accumulator
    float m = -1e30f, sum = 0.f;
    float acc[32] = {};
    for (int j = 0; j < NTOK; j++) {
        float s = 0.f;
        #pragma unroll
        for (int d = 0; d < 32; d += 4) {
            float4 kv = *(const float4*)&kbuf[j * 32 + d];
            s += qr[d] * kv.x + qr[d+1] * kv.y + qr[d+2] * kv.z + qr[d+3] * kv.w;
        }
        int tj = j >> 4, hj = (j >> 2) & 3, wj = j & 3;
        int idx = (dti - tj) * 15 + (dhi - hj) * 7 + (dwi - wj);
        s += rpbh[idx];
        if (labels[j] != li) s -= 100.0f;

        float newm = fmaxf(m, s);
        float corr = __expf(m - newm);     // m==-1e30 first iter: exp(-inf)=0, acc/sum zeroed correctly
        float p    = __expf(s - newm);
        sum = sum * corr + p;
        m = newm;
        #pragma unroll
        for (int d = 0; d < 32; d += 4) {
            float4 vv = *(const float4*)&vbuf[j * 32 + d];
            acc[d]   = acc[d]   * corr + p * vv.x;
            acc[d+1] = acc[d+1] * corr + p * vv.y;
            acc[d+2] = acc[d+2] * corr + p * vv.z;
            acc[d+3] = acc[d+3] * corr + p * vv.w;
        }
    }
    float inv = 1.0f / sum;
    // write (row, head*32+d) of attn_out (C-major rows)
    float* op = out + (size_t)(win * NTOK + i) * C_ + head * HD_;
    #pragma unroll
    for (int d = 0; d < 32; d += 4) {
        float4 o;
        o.x = acc[d] * inv; o.y = acc[d+1] * inv;
        o.z = acc[d+2] * inv; o.w = acc[d+3] * inv;
        *(float4*)(op + d) = o;
    }
}

// ---------------- launch ----------------
extern "C" void kernel_launch(void* const* d_in, const int* in_sizes, int n_in,
                              void* d_out, int out_size) {
    const float* x      = (const float*)d_in[0];
    const float* n1g    = (const float*)d_in[1];
    const float* n1b    = (const float*)d_in[2];
    const float* qkv_w  = (const float*)d_in[3];
    const float* qkv_b  = (const float*)d_in[4];
    const float* rpb    = (const float*)d_in[5];
    const float* proj_w = (const float*)d_in[6];
    const float* proj_b = (const float*)d_in[7];
    const float* n2g    = (const float*)d_in[8];
    const float* n2b    = (const float*)d_in[9];
    const float* fc1_w  = (const float*)d_in[10];
    const float* fc1_b  = (const float*)d_in[11];
    const float* fc2_w  = (const float*)d_in[12];
    const float* fc2_b  = (const float*)d_in[13];
    float* out = (float*)d_out;

    float *buf1, *buf2, *x2;
    cudaGetSymbolAddress((void**)&buf1, g_buf1);
    cudaGetSymbolAddress((void**)&buf2, g_buf2);
    cudaGetSymbolAddress((void**)&x2,   g_x2);

    // 1) LN1 + cyclic shift + window partition -> buf1 (window rows, C)
    k_ln<true><<<ROWS, 192>>>(x, n1g, n1b, buf1);

    // 2) QKV GEMM -> buf2 (window rows, 576)
    { dim3 g(C3 / 64, ROWS / 64); k_gemm<0><<<g, 256>>>(buf1, qkv_w, qkv_b, buf2, ROWS, C3, C_, nullptr); }

    // 3) windowed attention (rpb + shift mask + online softmax + @V) -> buf1 (window rows, C)
    k_attn<<<BATCH * NWIN * NH_, NTOK>>>(buf2, rpb, buf1);

    // 4) proj GEMM + window reverse + roll-back + residual -> x2 (natural rows, C)
    { dim3 g(C_ / 64, ROWS / 64); k_gemm<1><<<g, 256>>>(buf1, proj_w, proj_b, x2, ROWS, C_, C_, x); }

    // 5) LN2 -> buf1
    k_ln<false><<<ROWS, 192>>>(x2, n2g, n2b, buf1);

    // 6) fc1 GEMM + exact GELU -> buf2 (natural rows, 768)
    { dim3 g(CM_ / 64, ROWS / 64); k_gemm<2><<<g, 256>>>(buf1, fc1_w, fc1_b, buf2, ROWS, CM_, C_, nullptr); }

    // 7) fc2 GEMM + residual -> d_out
    { dim3 g(C_ / 64, ROWS / 64); k_gemm<3><<<g, 256>>>(buf2, fc2_w, fc2_b, out, ROWS, C_, CM_, x2); }
}

// round 5
// speedup vs baseline: 1.6342x; 1.6342x over previous
#include <cuda_runtime.h>
#include <cuda_bf16.h>
#include <math.h>
#include <stdint.h>

// ---------------- problem constants ----------------
#define BATCH 2
#define T_    64
#define H_    32
#define W_    32
#define C_    192
#define L_    (T_*H_*W_)
#define ROWS  (BATCH*L_)        // 131072 rows
#define NH_   6
#define HD_   32
#define NTOK  128
#define NWIN  512
#define C3    576
#define CM_   768
#define SCALE_ 0.17677669529663687f

// ---------------- scratch ----------------
__device__ __nv_bfloat16 g_act_hi[(size_t)ROWS * C_];
__device__ __nv_bfloat16 g_act_lo[(size_t)ROWS * C_];
__device__ __nv_bfloat16 g_hid_hi[(size_t)ROWS * CM_];
__device__ __nv_bfloat16 g_hid_lo[(size_t)ROWS * CM_];
__device__ float         g_qkv  [(size_t)ROWS * C3];
__device__ float         g_x2   [(size_t)ROWS * C_];
__device__ __nv_bfloat16 g_w_hi[442368];
__device__ __nv_bfloat16 g_w_lo[442368];

// ---------------- helpers ----------------
__device__ __forceinline__ uint32_t smem_u32(const void* p) {
    uint32_t a;
    asm("{ .reg .u64 t; cvta.to.shared.u64 t, %1; cvt.u32.u64 %0, t; }" : "=r"(a) : "l"(p));
    return a;
}
#define CPA16(dst, src) asm volatile("cp.async.cg.shared.global [%0], [%1], 16;" :: "r"(dst), "l"(src))
#define CPA_COMMIT()    asm volatile("cp.async.commit_group;" ::: "memory")
#define CPA_WAIT0()     asm volatile("cp.async.wait_group 0;" ::: "memory")
#define LDM4(d0,d1,d2,d3,addr) \
    asm volatile("ldmatrix.sync.aligned.m8n8.x4.shared.b16 {%0,%1,%2,%3}, [%4];" \
        : "=r"(d0), "=r"(d1), "=r"(d2), "=r"(d3) : "r"(addr))

__device__ __forceinline__ void mma_bf16(float* c, const uint32_t* a, const uint32_t* b) {
    asm volatile("mma.sync.aligned.m16n8k16.row.col.f32.bf16.bf16.f32 "
        "{%0,%1,%2,%3},{%4,%5,%6,%7},{%8,%9},{%0,%1,%2,%3};"
        : "+f"(c[0]), "+f"(c[1]), "+f"(c[2]), "+f"(c[3])
        : "r"(a[0]), "r"(a[1]), "r"(a[2]), "r"(a[3]), "r"(b[0]), "r"(b[1]));
}

__device__ __forceinline__ size_t shifted_pos(int row) {
    int win = row >> 7, n = row & 127;
    int b  = win >> 9, widx = win & 511;
    int tb = widx >> 6, hb = (widx >> 3) & 7, wb = widx & 7;
    int ti = n >> 4,   hi = (n >> 2) & 3,    wi = n & 3;
    int t  = (tb*8 + ti + 4) & 63;
    int hh = (hb*4 + hi + 2) & 31;
    int ww = (wb*4 + wi + 2) & 31;
    return (size_t)b * L_ + (size_t)t * (H_*W_) + hh * W_ + ww;
}

__device__ __forceinline__ void split_bf16(float v, __nv_bfloat16& h, __nv_bfloat16& l) {
    h = __float2bfloat16(v);
    l = __float2bfloat16(v - __bfloat162float(h));
}

// ---------------- weight convert+transpose: W[K,N] fp32 -> Bt[N,K] bf16 hi/lo ----------------
__global__ void k_wconv(const float* __restrict__ W, __nv_bfloat16* __restrict__ hi,
                        __nv_bfloat16* __restrict__ lo, int K, int N) {
    int idx = blockIdx.x * 256 + threadIdx.x;
    if (idx >= K * N) return;
    int n = idx / K, k = idx - n * K;
    float v = W[(size_t)k * N + n];
    __nv_bfloat16 h, l; split_bf16(v, h, l);
    hi[idx] = h; lo[idx] = l;
}

// ---------------- layernorm -> bf16 hi/lo ----------------
template<bool SHIFTMAP>
__global__ void k_ln(const float* __restrict__ x, const float* __restrict__ g,
                     const float* __restrict__ bt,
                     __nv_bfloat16* __restrict__ ohi, __nv_bfloat16* __restrict__ olo) {
    int r = blockIdx.x;
    int c = threadIdx.x;
    size_t src = SHIFTMAP ? shifted_pos(r) * C_ : (size_t)r * C_;
    float v = x[src + c];
    float s1 = v, s2 = v * v;
    #pragma unroll
    for (int off = 16; off; off >>= 1) {
        s1 += __shfl_down_sync(0xffffffffu, s1, off);
        s2 += __shfl_down_sync(0xffffffffu, s2, off);
    }
    __shared__ float red[12];
    int warp = c >> 5, lane = c & 31;
    if (lane == 0) { red[warp] = s1; red[6 + warp] = s2; }
    __syncthreads();
    if (c == 0) {
        float a = 0.f, bb = 0.f;
        #pragma unroll
        for (int w2 = 0; w2 < 6; w2++) { a += red[w2]; bb += red[6 + w2]; }
        red[0] = a; red[6] = bb;
    }
    __syncthreads();
    float mu   = red[0] * (1.0f / 192.0f);
    float var  = red[6] * (1.0f / 192.0f) - mu * mu;
    float rstd = rsqrtf(var + 1e-5f);
    float y = (v - mu) * rstd * g[c] + bt[c];
    __nv_bfloat16 h, l; split_bf16(y, h, l);
    ohi[(size_t)r * C_ + c] = h;
    olo[(size_t)r * C_ + c] = l;
}

// ---------------- HMMA bf16x3 GEMM: CTA 128x96, 8 warps (4m x 2n) of 32x48, k-step 16 ----------------
// MODE 0: outf = A*B + bias                     (qkv)
// MODE 1: outf[pos] = res[pos] + A*B + bias     (proj + reverse + roll + residual)
// MODE 2: (ohi,olo) = split(gelu(A*B + bias))   (fc1)
// MODE 3: outf = res + A*B + bias               (fc2 + residual)
#define ASTRIDE 48
template<int MODE>
__global__ __launch_bounds__(256) void k_mma_gemm(
    const __nv_bfloat16* __restrict__ Ahi, const __nv_bfloat16* __restrict__ Alo,
    const __nv_bfloat16* __restrict__ Bhi, const __nv_bfloat16* __restrict__ Blo,
    const float* __restrict__ bias, int K, int Ntot,
    float* __restrict__ outf,
    __nv_bfloat16* __restrict__ ohi, __nv_bfloat16* __restrict__ olo,
    const float* __restrict__ res)
{
    __shared__ __align__(16) uint8_t sAh[2 * 128 * ASTRIDE];
    __shared__ __align__(16) uint8_t sAl[2 * 128 * ASTRIDE];
    __shared__ __align__(16) uint8_t sBh[2 * 96 * ASTRIDE];
    __shared__ __align__(16) uint8_t sBl[2 * 96 * ASTRIDE];

    const int tid = threadIdx.x;
    const int wid = tid >> 5, lane = tid & 31;
    const int wm = wid & 3, wn = wid >> 2;
    const int bm = blockIdx.y * 128;
    const int bn = blockIdx.x * 96;
    const uint32_t aH = smem_u32(sAh), aL = smem_u32(sAl);
    const uint32_t bH = smem_u32(sBh), bL = smem_u32(sBl);
    const int NC = K >> 4;

    float acc[2][6][4];
    #pragma unroll
    for (int i = 0; i < 2; i++)
        #pragma unroll
        for (int j = 0; j < 6; j++)
            #pragma unroll
            for (int q = 0; q < 4; q++) acc[i][j][q] = 0.f;

    // ---- stage loader ----
    auto load_stage = [&](int c, int s) {
        const int k0 = c << 4;
        // A: 128 rows x 2 chunks x {hi,lo}
        {
            int r = tid & 127, ch = (tid >> 7) & 1;
            uint32_t d = (uint32_t)(s * 128 * ASTRIDE + r * ASTRIDE + ch * 16);
            const __nv_bfloat16* s0 = Ahi + (size_t)(bm + r) * K + k0 + ch * 8;
            const __nv_bfloat16* s1 = Alo + (size_t)(bm + r) * K + k0 + ch * 8;
            CPA16(aH + d, s0);
            CPA16(aL + d, s1);
        }
        // B: 96 rows x 2 chunks x {hi,lo} = 384 tasks
        #pragma unroll
        for (int t = tid; t < 384; t += 256) {
            int arr = t >= 192;
            int u = t - arr * 192;
            int r = u >> 1, ch = u & 1;
            uint32_t d = (uint32_t)(s * 96 * ASTRIDE + r * ASTRIDE + ch * 16);
            const __nv_bfloat16* sp = (arr ? Blo : Bhi) + (size_t)(bn + r) * K + k0 + ch * 8;
            CPA16((arr ? bL : bH) + d, sp);
        }
        CPA_COMMIT();
    };

    load_stage(0, 0);

    const int arow = wm * 32 + (lane & 15);
    const uint32_t aoff = ((uint32_t)lane >> 4) * 16;
    const int g = lane >> 3;
    const int brow = wn * 48 + ((g >> 1) << 3) + (lane & 7);
    const uint32_t boff = (uint32_t)(g & 1) * 16;

    for (int c = 0; c < NC; c++) {
        const int s = c & 1;
        CPA_WAIT0();
        __syncthreads();
        if (c + 1 < NC) load_stage(c + 1, s ^ 1);

        uint32_t ah[2][4], al[2][4], bh[3][4], bl[3][4];
        #pragma unroll
        for (int mt = 0; mt < 2; mt++) {
            uint32_t ad = (uint32_t)(s * 128 * ASTRIDE + (arow + mt * 16) * ASTRIDE) + aoff;
            LDM4(ah[mt][0], ah[mt][1], ah[mt][2], ah[mt][3], aH + ad);
            LDM4(al[mt][0], al[mt][1], al[mt][2], al[mt][3], aL + ad);
        }
        #pragma unroll
        for (int p = 0; p < 3; p++) {
            uint32_t bd = (uint32_t)(s * 96 * ASTRIDE + (brow + p * 16) * ASTRIDE) + boff;
            LDM4(bh[p][0], bh[p][1], bh[p][2], bh[p][3], bH + bd);
            LDM4(bl[p][0], bl[p][1], bl[p][2], bl[p][3], bL + bd);
        }
        #pragma unroll
        for (int mt = 0; mt < 2; mt++)
            #pragma unroll
            for (int p = 0; p < 3; p++)
                #pragma unroll
                for (int q = 0; q < 2; q++) {
                    float* d = acc[mt][p * 2 + q];
                    mma_bf16(d, ah[mt], &bh[p][q * 2]);
                    mma_bf16(d, ah[mt], &bl[p][q * 2]);
                    mma_bf16(d, al[mt], &bh[p][q * 2]);
                }
        __syncthreads();
    }

    // ---- epilogue ----
    const float* biasp = bias + bn;
    #pragma unroll
    for (int mt = 0; mt < 2; mt++) {
        #pragma unroll
        for (int ro = 0; ro < 2; ro++) {
            int grow = bm + wm * 32 + mt * 16 + (lane >> 2) + ro * 8;
            size_t dstbase;
            if (MODE == 1)      dstbase = shifted_pos(grow) * (size_t)192;
            else if (MODE == 2) dstbase = (size_t)grow * CM_;
            else                dstbase = (size_t)grow * Ntot;
            #pragma unroll
            for (int nt = 0; nt < 6; nt++) {
                int col = wn * 48 + nt * 8 + (lane & 3) * 2;
                float v0 = acc[mt][nt][ro * 2 + 0] + __ldg(biasp + col);
                float v1 = acc[mt][nt][ro * 2 + 1] + __ldg(biasp + col + 1);
                size_t oi = dstbase + bn + col;
                if (MODE == 2) {
                    v0 = 0.5f * v0 * (1.0f + erff(v0 * 0.70710678118654752f));
                    v1 = 0.5f * v1 * (1.0f + erff(v1 * 0.70710678118654752f));
                    __nv_bfloat16 h0, l0, h1, l1;
                    split_bf16(v0, h0, l0); split_bf16(v1, h1, l1);
                    *(__nv_bfloat162*)&ohi[oi] = __halves2bfloat162(h0, h1);
                    *(__nv_bfloat162*)&olo[oi] = __halves2bfloat162(l0, l1);
                } else if (MODE == 0) {
                    float2 v; v.x = v0; v.y = v1;
                    *(float2*)&outf[oi] = v;
                } else {
                    float2 rv = *(const float2*)&res[oi];
                    float2 v; v.x = rv.x + v0; v.y = rv.y + v1;
                    *(float2*)&outf[oi] = v;
                }
            }
        }
    }
}

// ---------------- fused window attention (online softmax), emits bf16 hi/lo ----------------
__global__ void k_attn(const float* __restrict__ qkv,
                       const float* __restrict__ rpb_table,
                       __nv_bfloat16* __restrict__ ohi, __nv_bfloat16* __restrict__ olo) {
    __shared__ float kbuf[NTOK * HD_];
    __shared__ float vbuf[NTOK * HD_];
    __shared__ float rpbh[736];
    __shared__ int   labels[NTOK];

    int blk  = blockIdx.x;
    int win  = blk / NH_, head = blk % NH_;
    int i    = threadIdx.x;
    size_t base = (size_t)win * NTOK * C3 + head * HD_;

    {
        int d4 = (i & 7) * 4;
        for (int j = i >> 3; j < NTOK; j += 16) {
            const float* p = qkv + base + (size_t)j * C3;
            *(float4*)&kbuf[j * 32 + d4] = *(const float4*)(p + 192 + d4);
            *(float4*)&vbuf[j * 32 + d4] = *(const float4*)(p + 384 + d4);
        }
    }
    for (int t = i; t < 735; t += NTOK) rpbh[t] = rpb_table[t * NH_ + head];

    int widx = win & 511;
    int tb = widx >> 6, hb = (widx >> 3) & 7, wb = widx & 7;
    int ti = i >> 4, hi = (i >> 2) & 3, wi = i & 3;
    {
        int gt = tb * 8 + ti, gh = hb * 4 + hi, gw = wb * 4 + wi;
        int rt = (gt < 56) ? 0 : (gt < 60 ? 1 : 2);
        int rh = (gh < 28) ? 0 : (gh < 30 ? 1 : 2);
        int rw = (gw < 28) ? 0 : (gw < 30 ? 1 : 2);
        labels[i] = rt * 9 + rh * 3 + rw;
    }
    __syncthreads();

    float qr[32];
    {
        const float* qp = qkv + base + (size_t)i * C3;
        #pragma unroll
        for (int d = 0; d < 32; d += 4) {
            float4 t4 = *(const float4*)(qp + d);
            qr[d] = t4.x * SCALE_; qr[d+1] = t4.y * SCALE_;
            qr[d+2] = t4.z * SCALE_; qr[d+3] = t4.w * SCALE_;
        }
    }
    int li  = labels[i];
    int dti = ti + 7, dhi = hi + 3, dwi = wi + 3;

    float m = -1e30f, sum = 0.f;
    float acc[32] = {};
    for (int j = 0; j < NTOK; j++) {
        float s = 0.f;
        #pragma unroll
        for (int d = 0; d < 32; d += 4) {
            float4 kv = *(const float4*)&kbuf[j * 32 + d];
            s += qr[d] * kv.x + qr[d+1] * kv.y + qr[d+2] * kv.z + qr[d+3] * kv.w;
        }
        int tj = j >> 4, hj = (j >> 2) & 3, wj = j & 3;
        int idx = (dti - tj) * 15 + (dhi - hj) * 7 + (dwi - wj);
        s += rpbh[idx];
        if (labels[j] != li) s -= 100.0f;

        float newm = fmaxf(m, s);
        float corr = __expf(m - newm);
        float p    = __expf(s - newm);
        sum = sum * corr + p;
        m = newm;
        #pragma unroll
        for (int d = 0; d < 32; d += 4) {
            float4 vv = *(const float4*)&vbuf[j * 32 + d];
            acc[d]   = acc[d]   * corr + p * vv.x;
            acc[d+1] = acc[d+1] * corr + p * vv.y;
            acc[d+2] = acc[d+2] * corr + p * vv.z;
            acc[d+3] = acc[d+3] * corr + p * vv.w;
        }
    }
    float inv = 1.0f / sum;
    size_t ob = (size_t)(win * NTOK + i) * C_ + head * HD_;
    #pragma unroll
    for (int d = 0; d < 32; d += 2) {
        float a = acc[d] * inv, b = acc[d+1] * inv;
        __nv_bfloat16 ah, al2, bh, bl2;
        split_bf16(a, ah, al2); split_bf16(b, bh, bl2);
        *(__nv_bfloat162*)&ohi[ob + d] = __halves2bfloat162(ah, bh);
        *(__nv_bfloat162*)&olo[ob + d] = __halves2bfloat162(al2, bl2);
    }
}

// ---------------- launch ----------------
extern "C" void kernel_launch(void* const* d_in, const int* in_sizes, int n_in,
                              void* d_out, int out_size) {
    const float* x      = (const float*)d_in[0];
    const float* n1g    = (const float*)d_in[1];
    const float* n1b    = (const float*)d_in[2];
    const float* qkv_w  = (const float*)d_in[3];
    const float* qkv_b  = (const float*)d_in[4];
    const float* rpb    = (const float*)d_in[5];
    const float* proj_w = (const float*)d_in[6];
    const float* proj_b = (const float*)d_in[7];
    const float* n2g    = (const float*)d_in[8];
    const float* n2b    = (const float*)d_in[9];
    const float* fc1_w  = (const float*)d_in[10];
    const float* fc1_b  = (const float*)d_in[11];
    const float* fc2_w  = (const float*)d_in[12];
    const float* fc2_b  = (const float*)d_in[13];
    float* out = (float*)d_out;

    __nv_bfloat16 *acthi, *actlo, *hidhi, *hidlo, *whi, *wlo;
    float *qkvb, *x2;
    cudaGetSymbolAddress((void**)&acthi, g_act_hi);
    cudaGetSymbolAddress((void**)&actlo, g_act_lo);
    cudaGetSymbolAddress((void**)&hidhi, g_hid_hi);
    cudaGetSymbolAddress((void**)&hidlo, g_hid_lo);
    cudaGetSymbolAddress((void**)&whi,   g_w_hi);
    cudaGetSymbolAddress((void**)&wlo,   g_w_lo);
    cudaGetSymbolAddress((void**)&qkvb,  g_qkv);
    cudaGetSymbolAddress((void**)&x2,    g_x2);

    const int OQKV = 0, OPROJ = 110592, OFC1 = 147456, OFC2 = 294912;

    k_wconv<<<(192*576 + 255)/256, 256>>>(qkv_w,  whi + OQKV,  wlo + OQKV,  192, 576);
    k_wconv<<<(192*192 + 255)/256, 256>>>(proj_w, whi + OPROJ, wlo + OPROJ, 192, 192);
    k_wconv<<<(192*768 + 255)/256, 256>>>(fc1_w,  whi + OFC1,  wlo + OFC1,  192, 768);
    k_wconv<<<(768*192 + 255)/256, 256>>>(fc2_w,  whi + OFC2,  wlo + OFC2,  768, 192);

    // 1) LN1 + shift + partition -> act hi/lo (window rows, C)
    k_ln<true><<<ROWS, 192>>>(x, n1g, n1b, acthi, actlo);

    // 2) QKV GEMM -> g_qkv fp32
    { dim3 g(C3/96, ROWS/128); k_mma_gemm<0><<<g, 256>>>(acthi, actlo, whi + OQKV, wlo + OQKV, qkv_b, 192, C3, qkvb, nullptr, nullptr, nullptr); }

    // 3) windowed attention -> act hi/lo
    k_attn<<<BATCH * NWIN * NH_, NTOK>>>(qkvb, rpb, acthi, actlo);

    // 4) proj GEMM + reverse + roll + residual -> x2 fp32
    { dim3 g(C_/96, ROWS/128); k_mma_gemm<1><<<g, 256>>>(acthi, actlo, whi + OPROJ, wlo + OPROJ, proj_b, 192, C_, x2, nullptr, nullptr, x); }

    // 5) LN2 -> act hi/lo
    k_ln<false><<<ROWS, 192>>>(x2, n2g, n2b, acthi, actlo);

    // 6) fc1 GEMM + GELU -> hidden hi/lo
    { dim3 g(CM_/96, ROWS/128); k_mma_gemm<2><<<g, 256>>>(acthi, actlo, whi + OFC1, wlo + OFC1, fc1_b, 192, CM_, nullptr, hidhi, hidlo, nullptr); }

    // 7) fc2 GEMM + residual -> d_out
    { dim3 g(C_/96, ROWS/128); k_mma_gemm<3><<<g, 256>>>(hidhi, hidlo, whi + OFC2, wlo + OFC2, fc2_b, 768, C_, out, nullptr, nullptr, x2); }
}

// round 6
// speedup vs baseline: 1.8826x; 1.1520x over previous
#include <cuda_runtime.h>
#include <cuda_fp16.h>
#include <math.h>
#include <stdint.h>

// ---------------- problem constants ----------------
#define BATCH 2
#define T_    64
#define H_    32
#define W_    32
#define C_    192
#define L_    (T_*H_*W_)
#define ROWS  (BATCH*L_)        // 131072 rows
#define NH_   6
#define HD_   32
#define NTOK  128
#define NWIN  512
#define C3    576
#define CM_   768
#define SCALE_ 0.17677669529663687f

// ---------------- scratch ----------------
__device__ __half g_act_hi[(size_t)ROWS * C_];
__device__ __half g_act_lo[(size_t)ROWS * C_];
__device__ __half g_hid_hi[(size_t)ROWS * CM_];
__device__ __half g_hid_lo[(size_t)ROWS * CM_];
__device__ float  g_qkv  [(size_t)ROWS * C3];
__device__ float  g_x2   [(size_t)ROWS * C_];
__device__ __half g_w    [442368];

// ---------------- helpers ----------------
__device__ __forceinline__ uint32_t smem_u32(const void* p) {
    uint32_t a;
    asm("{ .reg .u64 t; cvta.to.shared.u64 t, %1; cvt.u32.u64 %0, t; }" : "=r"(a) : "l"(p));
    return a;
}
#define CPA16(dst, src) asm volatile("cp.async.cg.shared.global [%0], [%1], 16;" :: "r"(dst), "l"(src))
#define CPA_COMMIT()    asm volatile("cp.async.commit_group;" ::: "memory")
#define CPA_WAIT0()     asm volatile("cp.async.wait_group 0;" ::: "memory")
#define LDM4(d0,d1,d2,d3,addr) \
    asm volatile("ldmatrix.sync.aligned.m8n8.x4.shared.b16 {%0,%1,%2,%3}, [%4];" \
        : "=r"(d0), "=r"(d1), "=r"(d2), "=r"(d3) : "r"(addr))

__device__ __forceinline__ void mma_f16(float* c, const uint32_t* a, const uint32_t* b) {
    asm volatile("mma.sync.aligned.m16n8k16.row.col.f32.f16.f16.f32 "
        "{%0,%1,%2,%3},{%4,%5,%6,%7},{%8,%9},{%0,%1,%2,%3};"
        : "+f"(c[0]), "+f"(c[1]), "+f"(c[2]), "+f"(c[3])
        : "r"(a[0]), "r"(a[1]), "r"(a[2]), "r"(a[3]), "r"(b[0]), "r"(b[1]));
}

__device__ __forceinline__ size_t shifted_pos(int row) {
    int win = row >> 7, n = row & 127;
    int b  = win >> 9, widx = win & 511;
    int tb = widx >> 6, hb = (widx >> 3) & 7, wb = widx & 7;
    int ti = n >> 4,   hi = (n >> 2) & 3,    wi = n & 3;
    int t  = (tb*8 + ti + 4) & 63;
    int hh = (hb*4 + hi + 2) & 31;
    int ww = (wb*4 + wi + 2) & 31;
    return (size_t)b * L_ + (size_t)t * (H_*W_) + hh * W_ + ww;
}

__device__ __forceinline__ void split_f16(float v, __half& h, __half& l) {
    h = __float2half_rn(v);
    l = __float2half_rn(v - __half2float(h));
}

// ---------------- weight convert+transpose (all 4 weights, one launch) ----------------
// W[K,N] fp32 -> Wt[N,K] fp16, packed at fixed offsets in g_w
__global__ void k_wconv_all(const float* __restrict__ qkv_w, const float* __restrict__ proj_w,
                            const float* __restrict__ fc1_w, const float* __restrict__ fc2_w,
                            __half* __restrict__ w) {
    int idx = blockIdx.x * 256 + threadIdx.x;
    if (idx >= 442368) return;
    const float* W; int K, N, off;
    if (idx < 110592)      { W = qkv_w;  K = 192; N = 576; off = 0; }
    else if (idx < 147456) { W = proj_w; K = 192; N = 192; off = 110592; }
    else if (idx < 294912) { W = fc1_w;  K = 192; N = 768; off = 147456; }
    else                   { W = fc2_w;  K = 768; N = 192; off = 294912; }
    int u = idx - off;
    int n = u / K, k = u - n * K;
    w[idx] = __float2half_rn(W[(size_t)k * N + n]);
}

// ---------------- layernorm -> fp16 hi/lo ----------------
template<bool SHIFTMAP>
__global__ void k_ln(const float* __restrict__ x, const float* __restrict__ g,
                     const float* __restrict__ bt,
                     __half* __restrict__ ohi, __half* __restrict__ olo) {
    int r = blockIdx.x;
    int c = threadIdx.x;
    size_t src = SHIFTMAP ? shifted_pos(r) * C_ : (size_t)r * C_;
    float v = x[src + c];
    float s1 = v, s2 = v * v;
    #pragma unroll
    for (int off = 16; off; off >>= 1) {
        s1 += __shfl_down_sync(0xffffffffu, s1, off);
        s2 += __shfl_down_sync(0xffffffffu, s2, off);
    }
    __shared__ float red[12];
    int warp = c >> 5, lane = c & 31;
    if (lane == 0) { red[warp] = s1; red[6 + warp] = s2; }
    __syncthreads();
    if (c == 0) {
        float a = 0.f, bb = 0.f;
        #pragma unroll
        for (int w2 = 0; w2 < 6; w2++) { a += red[w2]; bb += red[6 + w2]; }
        red[0] = a; red[6] = bb;
    }
    __syncthreads();
    float mu   = red[0] * (1.0f / 192.0f);
    float var  = red[6] * (1.0f / 192.0f) - mu * mu;
    float rstd = rsqrtf(var + 1e-5f);
    float y = (v - mu) * rstd * g[c] + bt[c];
    __half h, l; split_f16(y, h, l);
    ohi[(size_t)r * C_ + c] = h;
    olo[(size_t)r * C_ + c] = l;
}

// ---------------- HMMA fp16x2 GEMM: CTA 128x96, 8 warps (4m x 2n), k-step 16 ----------------
// A split hi/lo fp16 (22-bit effective), B single fp16. 2 MMA products per step.
// MODE 0: outf = A*B + bias                     (qkv)
// MODE 1: outf[pos] = res[pos] + A*B + bias     (proj + reverse + roll + residual)
// MODE 2: (ohi,olo) = split(gelu(A*B + bias))   (fc1)
// MODE 3: outf = res + A*B + bias               (fc2 + residual)
#define ASTRIDE 48
template<int MODE>
__global__ __launch_bounds__(256, 2) void k_mma_gemm(
    const __half* __restrict__ Ahi, const __half* __restrict__ Alo,
    const __half* __restrict__ Bw,
    const float* __restrict__ bias, int K, int Ntot,
    float* __restrict__ outf,
    __half* __restrict__ ohi, __half* __restrict__ olo,
    const float* __restrict__ res)
{
    __shared__ __align__(16) uint8_t sAh[2 * 128 * ASTRIDE];
    __shared__ __align__(16) uint8_t sAl[2 * 128 * ASTRIDE];
    __shared__ __align__(16) uint8_t sBh[2 * 96 * ASTRIDE];

    const int tid = threadIdx.x;
    const int wid = tid >> 5, lane = tid & 31;
    const int wm = wid & 3, wn = wid >> 2;
    const int bm = blockIdx.y * 128;
    const int bn = blockIdx.x * 96;
    const uint32_t aH = smem_u32(sAh), aL = smem_u32(sAl);
    const uint32_t bH = smem_u32(sBh);
    const int NC = K >> 4;

    float acc[2][6][4];
    #pragma unroll
    for (int i = 0; i < 2; i++)
        #pragma unroll
        for (int j = 0; j < 6; j++)
            #pragma unroll
            for (int q = 0; q < 4; q++) acc[i][j][q] = 0.f;

    auto load_stage = [&](int c, int s) {
        const int k0 = c << 4;
        {   // A: 128 rows x 2 chunks, hi + lo
            int r = tid & 127, ch = (tid >> 7) & 1;
            uint32_t d = (uint32_t)(s * 128 * ASTRIDE + r * ASTRIDE + ch * 16);
            CPA16(aH + d, Ahi + (size_t)(bm + r) * K + k0 + ch * 8);
            CPA16(aL + d, Alo + (size_t)(bm + r) * K + k0 + ch * 8);
        }
        if (tid < 192) {  // B: 96 rows x 2 chunks
            int r = tid >> 1, ch = tid & 1;
            uint32_t d = (uint32_t)(s * 96 * ASTRIDE + r * ASTRIDE + ch * 16);
            CPA16(bH + d, Bw + (size_t)(bn + r) * K + k0 + ch * 8);
        }
        CPA_COMMIT();
    };

    load_stage(0, 0);

    const int arow = wm * 32 + (lane & 15);
    const uint32_t aoff = ((uint32_t)lane >> 4) * 16;
    const int g = lane >> 3;
    const int brow = wn * 48 + ((g >> 1) << 3) + (lane & 7);
    const uint32_t boff = (uint32_t)(g & 1) * 16;

    for (int c = 0; c < NC; c++) {
        const int s = c & 1;
        CPA_WAIT0();
        __syncthreads();
        if (c + 1 < NC) load_stage(c + 1, s ^ 1);

        uint32_t ah[2][4], al[2][4], bh[3][4];
        #pragma unroll
        for (int mt = 0; mt < 2; mt++) {
            uint32_t ad = (uint32_t)(s * 128 * ASTRIDE + (arow + mt * 16) * ASTRIDE) + aoff;
            LDM4(ah[mt][0], ah[mt][1], ah[mt][2], ah[mt][3], aH + ad);
            LDM4(al[mt][0], al[mt][1], al[mt][2], al[mt][3], aL + ad);
        }
        #pragma unroll
        for (int p = 0; p < 3; p++) {
            uint32_t bd = (uint32_t)(s * 96 * ASTRIDE + (brow + p * 16) * ASTRIDE) + boff;
            LDM4(bh[p][0], bh[p][1], bh[p][2], bh[p][3], bH + bd);
        }
        #pragma unroll
        for (int mt = 0; mt < 2; mt++)
            #pragma unroll
            for (int p = 0; p < 3; p++)
                #pragma unroll
                for (int q = 0; q < 2; q++) {
                    float* d = acc[mt][p * 2 + q];
                    mma_f16(d, ah[mt], &bh[p][q * 2]);
                    mma_f16(d, al[mt], &bh[p][q * 2]);
                }
        __syncthreads();
    }

    // ---- epilogue ----
    const float* biasp = bias + bn;
    #pragma unroll
    for (int mt = 0; mt < 2; mt++) {
        #pragma unroll
        for (int ro = 0; ro < 2; ro++) {
            int grow = bm + wm * 32 + mt * 16 + (lane >> 2) + ro * 8;
            size_t dstbase;
            if (MODE == 1)      dstbase = shifted_pos(grow) * (size_t)192;
            else if (MODE == 2) dstbase = (size_t)grow * CM_;
            else                dstbase = (size_t)grow * Ntot;
            #pragma unroll
            for (int nt = 0; nt < 6; nt++) {
                int col = wn * 48 + nt * 8 + (lane & 3) * 2;
                float v0 = acc[mt][nt][ro * 2 + 0] + __ldg(biasp + col);
                float v1 = acc[mt][nt][ro * 2 + 1] + __ldg(biasp + col + 1);
                size_t oi = dstbase + bn + col;
                if (MODE == 2) {
                    v0 = 0.5f * v0 * (1.0f + erff(v0 * 0.70710678118654752f));
                    v1 = 0.5f * v1 * (1.0f + erff(v1 * 0.70710678118654752f));
                    __half h0, l0, h1, l1;
                    split_f16(v0, h0, l0); split_f16(v1, h1, l1);
                    *(__half2*)&ohi[oi] = __halves2half2(h0, h1);
                    *(__half2*)&olo[oi] = __halves2half2(l0, l1);
                } else if (MODE == 0) {
                    float2 v; v.x = v0; v.y = v1;
                    *(float2*)&outf[oi] = v;
                } else {
                    float2 rv = *(const float2*)&res[oi];
                    float2 v; v.x = rv.x + v0; v.y = rv.y + v1;
                    *(float2*)&outf[oi] = v;
                }
            }
        }
    }
}

// ---------------- fused window attention: chunked softmax (32-key chunks) ----------------
__global__ void k_attn(const float* __restrict__ qkv,
                       const float* __restrict__ rpb_table,
                       __half* __restrict__ ohi, __half* __restrict__ olo) {
    __shared__ float kbuf[NTOK * HD_];
    __shared__ float vbuf[NTOK * HD_];
    __shared__ float rpbh[736];
    __shared__ int   labels[NTOK];

    int blk  = blockIdx.x;
    int win  = blk / NH_, head = blk % NH_;
    int i    = threadIdx.x;
    size_t base = (size_t)win * NTOK * C3 + head * HD_;

    {
        int d4 = (i & 7) * 4;
        for (int j = i >> 3; j < NTOK; j += 16) {
            const float* p = qkv + base + (size_t)j * C3;
            *(float4*)&kbuf[j * 32 + d4] = *(const float4*)(p + 192 + d4);
            *(float4*)&vbuf[j * 32 + d4] = *(const float4*)(p + 384 + d4);
        }
    }
    for (int t = i; t < 735; t += NTOK) rpbh[t] = rpb_table[t * NH_ + head];

    int widx = win & 511;
    int tb = widx >> 6, hb = (widx >> 3) & 7, wb = widx & 7;
    int ti = i >> 4, hi = (i >> 2) & 3, wi = i & 3;
    {
        int gt = tb * 8 + ti, gh = hb * 4 + hi, gw = wb * 4 + wi;
        int rt = (gt < 56) ? 0 : (gt < 60 ? 1 : 2);
        int rh = (gh < 28) ? 0 : (gh < 30 ? 1 : 2);
        int rw = (gw < 28) ? 0 : (gw < 30 ? 1 : 2);
        labels[i] = rt * 9 + rh * 3 + rw;
    }
    __syncthreads();

    float qr[32];
    {
        const float* qp = qkv + base + (size_t)i * C3;
        #pragma unroll
        for (int d = 0; d < 32; d += 4) {
            float4 t4 = *(const float4*)(qp + d);
            qr[d] = t4.x * SCALE_; qr[d+1] = t4.y * SCALE_;
            qr[d+2] = t4.z * SCALE_; qr[d+3] = t4.w * SCALE_;
        }
    }
    int li  = labels[i];
    int dti = ti + 7, dhi = hi + 3, dwi = wi + 3;

    float m = -1e30f, sum = 0.f;
    float acc[32] = {};
    for (int cch = 0; cch < 4; cch++) {
        float sc[32];
        float cmax = -1e30f;
        #pragma unroll 8
        for (int jj = 0; jj < 32; jj++) {
            int j = cch * 32 + jj;
            float s = 0.f;
            #pragma unroll
            for (int d = 0; d < 32; d += 4) {
                float4 kv = *(const float4*)&kbuf[j * 32 + d];
                s += qr[d] * kv.x + qr[d+1] * kv.y + qr[d+2] * kv.z + qr[d+3] * kv.w;
            }
            int tj = j >> 4, hj = (j >> 2) & 3, wj = j & 3;
            int idx = (dti - tj) * 15 + (dhi - hj) * 7 + (dwi - wj);
            s += rpbh[idx];
            if (labels[j] != li) s -= 100.0f;
            sc[jj] = s;
            cmax = fmaxf(cmax, s);
        }
        float newm = fmaxf(m, cmax);
        float corr = __expf(m - newm);   // chunk 0: exp(-inf)=0 zeroes sum/acc correctly
        sum *= corr;
        #pragma unroll
        for (int d = 0; d < 32; d++) acc[d] *= corr;
        #pragma unroll 8
        for (int jj = 0; jj < 32; jj++) {
            int j = cch * 32 + jj;
            float p = __expf(sc[jj] - newm);
            sum += p;
            #pragma unroll
            for (int d = 0; d < 32; d += 4) {
                float4 vv = *(const float4*)&vbuf[j * 32 + d];
                acc[d]   += p * vv.x; acc[d+1] += p * vv.y;
                acc[d+2] += p * vv.z; acc[d+3] += p * vv.w;
            }
        }
        m = newm;
    }
    float inv = 1.0f / sum;
    size_t ob = (size_t)(win * NTOK + i) * C_ + head * HD_;
    #pragma unroll
    for (int d = 0; d < 32; d += 2) {
        float a = acc[d] * inv, b = acc[d+1] * inv;
        __half ah2, al2, bh2, bl2;
        split_f16(a, ah2, al2); split_f16(b, bh2, bl2);
        *(__half2*)&ohi[ob + d] = __halves2half2(ah2, bh2);
        *(__half2*)&olo[ob + d] = __halves2half2(al2, bl2);
    }
}

// ---------------- launch ----------------
extern "C" void kernel_launch(void* const* d_in, const int* in_sizes, int n_in,
                              void* d_out, int out_size) {
    const float* x      = (const float*)d_in[0];
    const float* n1g    = (const float*)d_in[1];
    const float* n1b    = (const float*)d_in[2];
    const float* qkv_w  = (const float*)d_in[3];
    const float* qkv_b  = (const float*)d_in[4];
    const float* rpb    = (const float*)d_in[5];
    const float* proj_w = (const float*)d_in[6];
    const float* proj_b = (const float*)d_in[7];
    const float* n2g    = (const float*)d_in[8];
    const float* n2b    = (const float*)d_in[9];
    const float* fc1_w  = (const float*)d_in[10];
    const float* fc1_b  = (const float*)d_in[11];
    const float* fc2_w  = (const float*)d_in[12];
    const float* fc2_b  = (const float*)d_in[13];
    float* out = (float*)d_out;

    __half *acthi, *actlo, *hidhi, *hidlo, *w;
    float *qkvb, *x2;
    cudaGetSymbolAddress((void**)&acthi, g_act_hi);
    cudaGetSymbolAddress((void**)&actlo, g_act_lo);
    cudaGetSymbolAddress((void**)&hidhi, g_hid_hi);
    cudaGetSymbolAddress((void**)&hidlo, g_hid_lo);
    cudaGetSymbolAddress((void**)&w,     g_w);
    cudaGetSymbolAddress((void**)&qkvb,  g_qkv);
    cudaGetSymbolAddress((void**)&x2,    g_x2);

    const int OQKV = 0, OPROJ = 110592, OFC1 = 147456, OFC2 = 294912;

    k_wconv_all<<<(442368 + 255)/256, 256>>>(qkv_w, proj_w, fc1_w, fc2_w, w);

    // 1) LN1 + shift + partition -> act hi/lo (window rows, C)
    k_ln<true><<<ROWS, 192>>>(x, n1g, n1b, acthi, actlo);

    // 2) QKV GEMM -> g_qkv fp32
    { dim3 g(C3/96, ROWS/128); k_mma_gemm<0><<<g, 256>>>(acthi, actlo, w + OQKV, qkv_b, 192, C3, qkvb, nullptr, nullptr, nullptr); }

    // 3) windowed attention -> act hi/lo
    k_attn<<<BATCH * NWIN * NH_, NTOK>>>(qkvb, rpb, acthi, actlo);

    // 4) proj GEMM + reverse + roll + residual -> x2 fp32
    { dim3 g(C_/96, ROWS/128); k_mma_gemm<1><<<g, 256>>>(acthi, actlo, w + OPROJ, proj_b, 192, C_, x2, nullptr, nullptr, x); }

    // 5) LN2 -> act hi/lo
    k_ln<false><<<ROWS, 192>>>(x2, n2g, n2b, acthi, actlo);

    // 6) fc1 GEMM + GELU -> hidden hi/lo
    { dim3 g(CM_/96, ROWS/128); k_mma_gemm<2><<<g, 256>>>(acthi, actlo, w + OFC1, fc1_b, 192, CM_, nullptr, hidhi, hidlo, nullptr); }

    // 7) fc2 GEMM + residual -> d_out
    { dim3 g(C_/96, ROWS/128); k_mma_gemm<3><<<g, 256>>>(hidhi, hidlo, w + OFC2, fc2_b, 768, C_, out, nullptr, nullptr, x2); }
}

// round 8
// speedup vs baseline: 2.0338x; 1.0803x over previous
#include <cuda_runtime.h>
#include <cuda_fp16.h>
#include <math.h>
#include <stdint.h>

// ---------------- problem constants ----------------
#define BATCH 2
#define T_    64
#define H_    32
#define W_    32
#define C_    192
#define L_    (T_*H_*W_)
#define ROWS  (BATCH*L_)        // 131072 rows
#define NH_   6
#define HD_   32
#define NTOK  128
#define NWIN  512
#define C3    576
#define CM_   768
#define SCALE_ 0.17677669529663687f

// ---------------- scratch ----------------
__device__ __half g_act_hi[(size_t)ROWS * C_];
__device__ __half g_act_lo[(size_t)ROWS * C_];
__device__ __half g_hid_hi[(size_t)ROWS * CM_];
__device__ __half g_hid_lo[(size_t)ROWS * CM_];
__device__ __half g_qkvh [(size_t)ROWS * C3];
__device__ float  g_x2   [(size_t)ROWS * C_];
__device__ __half g_w    [442368];

// ---------------- helpers ----------------
__device__ __forceinline__ uint32_t smem_u32(const void* p) {
    uint32_t a;
    asm("{ .reg .u64 t; cvta.to.shared.u64 t, %1; cvt.u32.u64 %0, t; }" : "=r"(a) : "l"(p));
    return a;
}
#define CPA16(dst, src) asm volatile("cp.async.cg.shared.global [%0], [%1], 16;" :: "r"(dst), "l"(src))
#define CPA_COMMIT()    asm volatile("cp.async.commit_group;" ::: "memory")
#define CPA_WAIT0()     asm volatile("cp.async.wait_group 0;" ::: "memory")
#define LDM4(d0,d1,d2,d3,addr) \
    asm volatile("ldmatrix.sync.aligned.m8n8.x4.shared.b16 {%0,%1,%2,%3}, [%4];" \
        : "=r"(d0), "=r"(d1), "=r"(d2), "=r"(d3) : "r"(addr))

__device__ __forceinline__ void mma_f16(float* c, const uint32_t* a, const uint32_t* b) {
    asm volatile("mma.sync.aligned.m16n8k16.row.col.f32.f16.f16.f32 "
        "{%0,%1,%2,%3},{%4,%5,%6,%7},{%8,%9},{%0,%1,%2,%3};"
        : "+f"(c[0]), "+f"(c[1]), "+f"(c[2]), "+f"(c[3])
        : "r"(a[0]), "r"(a[1]), "r"(a[2]), "r"(a[3]), "r"(b[0]), "r"(b[1]));
}

__device__ __forceinline__ size_t shifted_pos(int row) {
    int win = row >> 7, n = row & 127;
    int b  = win >> 9, widx = win & 511;
    int tb = widx >> 6, hb = (widx >> 3) & 7, wb = widx & 7;
    int ti = n >> 4,   hi = (n >> 2) & 3,    wi = n & 3;
    int t  = (tb*8 + ti + 4) & 63;
    int hh = (hb*4 + hi + 2) & 31;
    int ww = (wb*4 + wi + 2) & 31;
    return (size_t)b * L_ + (size_t)t * (H_*W_) + hh * W_ + ww;
}

__device__ __forceinline__ void split_f16(float v, __half& h, __half& l) {
    h = __float2half_rn(v);
    l = __float2half_rn(v - __half2float(h));
}

// ---------------- weight convert+transpose (all 4 weights) ----------------
__global__ void k_wconv_all(const float* __restrict__ qkv_w, const float* __restrict__ proj_w,
                            const float* __restrict__ fc1_w, const float* __restrict__ fc2_w,
                            __half* __restrict__ w) {
    int idx = blockIdx.x * 256 + threadIdx.x;
    if (idx >= 442368) return;
    const float* W; int K, N, off;
    if (idx < 110592)      { W = qkv_w;  K = 192; N = 576; off = 0; }
    else if (idx < 147456) { W = proj_w; K = 192; N = 192; off = 110592; }
    else if (idx < 294912) { W = fc1_w;  K = 192; N = 768; off = 147456; }
    else                   { W = fc2_w;  K = 768; N = 192; off = 294912; }
    int u = idx - off;
    int n = u / K, k = u - n * K;
    w[idx] = __float2half_rn(W[(size_t)k * N + n]);
}

// ---------------- layernorm -> fp16 hi/lo ----------------
template<bool SHIFTMAP>
__global__ void k_ln(const float* __restrict__ x, const float* __restrict__ g,
                     const float* __restrict__ bt,
                     __half* __restrict__ ohi, __half* __restrict__ olo) {
    int r = blockIdx.x;
    int c = threadIdx.x;
    size_t src = SHIFTMAP ? shifted_pos(r) * C_ : (size_t)r * C_;
    float v = x[src + c];
    float s1 = v, s2 = v * v;
    #pragma unroll
    for (int off = 16; off; off >>= 1) {
        s1 += __shfl_down_sync(0xffffffffu, s1, off);
        s2 += __shfl_down_sync(0xffffffffu, s2, off);
    }
    __shared__ float red[12];
    int warp = c >> 5, lane = c & 31;
    if (lane == 0) { red[warp] = s1; red[6 + warp] = s2; }
    __syncthreads();
    if (c == 0) {
        float a = 0.f, bb = 0.f;
        #pragma unroll
        for (int w2 = 0; w2 < 6; w2++) { a += red[w2]; bb += red[6 + w2]; }
        red[0] = a; red[6] = bb;
    }
    __syncthreads();
    float mu   = red[0] * (1.0f / 192.0f);
    float var  = red[6] * (1.0f / 192.0f) - mu * mu;
    float rstd = rsqrtf(var + 1e-5f);
    float y = (v - mu) * rstd * g[c] + bt[c];
    __half h, l; split_f16(y, h, l);
    ohi[(size_t)r * C_ + c] = h;
    olo[(size_t)r * C_ + c] = l;
}

// ---------------- HMMA fp16x2 GEMM: CTA 128x96, 8 warps, k-step 16 ----------------
// MODE 0: oh16 = half(A*B + bias)               (qkv -> fp16)
// MODE 1: outf[pos] = res[pos] + A*B + bias     (proj + reverse + roll + residual)
// MODE 2: (ohi,olo) = split(gelu(A*B + bias))   (fc1)
// MODE 3: outf = res + A*B + bias               (fc2 + residual)
#define ASTRIDE 48
template<int MODE>
__global__ __launch_bounds__(256, 2) void k_mma_gemm(
    const __half* __restrict__ Ahi, const __half* __restrict__ Alo,
    const __half* __restrict__ Bw,
    const float* __restrict__ bias, int K, int Ntot,
    float* __restrict__ outf,
    __half* __restrict__ ohi, __half* __restrict__ olo,
    const float* __restrict__ res)
{
    __shared__ __align__(16) uint8_t sAh[2 * 128 * ASTRIDE];
    __shared__ __align__(16) uint8_t sAl[2 * 128 * ASTRIDE];
    __shared__ __align__(16) uint8_t sBh[2 * 96 * ASTRIDE];

    const int tid = threadIdx.x;
    const int wid = tid >> 5, lane = tid & 31;
    const int wm = wid & 3, wn = wid >> 2;
    const int bm = blockIdx.y * 128;
    const int bn = blockIdx.x * 96;
    const uint32_t aH = smem_u32(sAh), aL = smem_u32(sAl);
    const uint32_t bH = smem_u32(sBh);
    const int NC = K >> 4;

    float acc[2][6][4];
    #pragma unroll
    for (int i = 0; i < 2; i++)
        #pragma unroll
        for (int j = 0; j < 6; j++)
            #pragma unroll
            for (int q = 0; q < 4; q++) acc[i][j][q] = 0.f;

    auto load_stage = [&](int c, int s) {
        const int k0 = c << 4;
        {
            int r = tid & 127, ch = (tid >> 7) & 1;
            uint32_t d = (uint32_t)(s * 128 * ASTRIDE + r * ASTRIDE + ch * 16);
            CPA16(aH + d, Ahi + (size_t)(bm + r) * K + k0 + ch * 8);
            CPA16(aL + d, Alo + (size_t)(bm + r) * K + k0 + ch * 8);
        }
        if (tid < 192) {
            int r = tid >> 1, ch = tid & 1;
            uint32_t d = (uint32_t)(s * 96 * ASTRIDE + r * ASTRIDE + ch * 16);
            CPA16(bH + d, Bw + (size_t)(bn + r) * K + k0 + ch * 8);
        }
        CPA_COMMIT();
    };

    load_stage(0, 0);

    const int arow = wm * 32 + (lane & 15);
    const uint32_t aoff = ((uint32_t)lane >> 4) * 16;
    const int g = lane >> 3;
    const int brow = wn * 48 + ((g >> 1) << 3) + (lane & 7);
    const uint32_t boff = (uint32_t)(g & 1) * 16;

    for (int c = 0; c < NC; c++) {
        const int s = c & 1;
        CPA_WAIT0();
        __syncthreads();
        if (c + 1 < NC) load_stage(c + 1, s ^ 1);

        uint32_t ah[2][4], al[2][4], bh[3][4];
        #pragma unroll
        for (int mt = 0; mt < 2; mt++) {
            uint32_t ad = (uint32_t)(s * 128 * ASTRIDE + (arow + mt * 16) * ASTRIDE) + aoff;
            LDM4(ah[mt][0], ah[mt][1], ah[mt][2], ah[mt][3], aH + ad);
            LDM4(al[mt][0], al[mt][1], al[mt][2], al[mt][3], aL + ad);
        }
        #pragma unroll
        for (int p = 0; p < 3; p++) {
            uint32_t bd = (uint32_t)(s * 96 * ASTRIDE + (brow + p * 16) * ASTRIDE) + boff;
            LDM4(bh[p][0], bh[p][1], bh[p][2], bh[p][3], bH + bd);
        }
        #pragma unroll
        for (int mt = 0; mt < 2; mt++)
            #pragma unroll
            for (int p = 0; p < 3; p++)
                #pragma unroll
                for (int q = 0; q < 2; q++) {
                    float* d = acc[mt][p * 2 + q];
                    mma_f16(d, ah[mt], &bh[p][q * 2]);
                    mma_f16(d, al[mt], &bh[p][q * 2]);
                }
        __syncthreads();
    }

    // ---- epilogue ----
    const float* biasp = bias + bn;
    #pragma unroll
    for (int mt = 0; mt < 2; mt++) {
        #pragma unroll
        for (int ro = 0; ro < 2; ro++) {
            int grow = bm + wm * 32 + mt * 16 + (lane >> 2) + ro * 8;
            size_t dstbase;
            if (MODE == 1)      dstbase = shifted_pos(grow) * (size_t)192;
            else if (MODE == 2) dstbase = (size_t)grow * CM_;
            else                dstbase = (size_t)grow * Ntot;
            #pragma unroll
            for (int nt = 0; nt < 6; nt++) {
                int col = wn * 48 + nt * 8 + (lane & 3) * 2;
                float v0 = acc[mt][nt][ro * 2 + 0] + __ldg(biasp + col);
                float v1 = acc[mt][nt][ro * 2 + 1] + __ldg(biasp + col + 1);
                size_t oi = dstbase + bn + col;
                if (MODE == 0) {
                    *(__half2*)&ohi[oi] = __halves2half2(__float2half_rn(v0), __float2half_rn(v1));
                } else if (MODE == 2) {
                    v0 = 0.5f * v0 * (1.0f + erff(v0 * 0.70710678118654752f));
                    v1 = 0.5f * v1 * (1.0f + erff(v1 * 0.70710678118654752f));
                    __half h0, l0, h1, l1;
                    split_f16(v0, h0, l0); split_f16(v1, h1, l1);
                    *(__half2*)&ohi[oi] = __halves2half2(h0, h1);
                    *(__half2*)&olo[oi] = __halves2half2(l0, l1);
                } else {
                    float2 rv = *(const float2*)&res[oi];
                    float2 v; v.x = rv.x + v0; v.y = rv.y + v1;
                    *(float2*)&outf[oi] = v;
                }
            }
        }
    }
}

// ---------------- fused window attention: fp16 K (HFMA2 scores), fp32 V, chunk-8 softmax ----------------
__global__ __launch_bounds__(128) void k_attn(const __half* __restrict__ qkvh,
                       const float* __restrict__ rpb_table,
                       __half* __restrict__ ohi, __half* __restrict__ olo) {
    __shared__ __align__(16) __half khalf[NTOK * HD_];   // 8 KB
    __shared__ __align__(16) float  vbuf [NTOK * HD_];   // 16 KB
    __shared__ float rpbh[736];
    __shared__ int   labels[NTOK];

    int blk  = blockIdx.x;
    int win  = blk / NH_, head = blk % NH_;
    int i    = threadIdx.x;
    const __half* wbase = qkvh + (size_t)win * NTOK * C3 + head * HD_;

    // stage K (fp16) and V (fp16 -> fp32): 8 threads per row
    {
        int c = i & 7;
        for (int r = i >> 3; r < NTOK; r += 16) {
            const __half* p = wbase + (size_t)r * C3;
            if (c < 4) {
                *(uint4*)&khalf[r * 32 + c * 8] = *(const uint4*)(p + 192 + c * 8);
            } else {
                int cc = c - 4;
                uint4 raw = *(const uint4*)(p + 384 + cc * 8);
                __half2* h2 = (__half2*)&raw;
                float2 f0 = __half22float2(h2[0]), f1 = __half22float2(h2[1]);
                float2 f2 = __half22float2(h2[2]), f3 = __half22float2(h2[3]);
                float4 a; a.x = f0.x; a.y = f0.y; a.z = f1.x; a.w = f1.y;
                float4 b; b.x = f2.x; b.y = f2.y; b.z = f3.x; b.w = f3.y;
                *(float4*)&vbuf[r * 32 + cc * 8]     = a;
                *(float4*)&vbuf[r * 32 + cc * 8 + 4] = b;
            }
        }
    }
    for (int t = i; t < 735; t += NTOK) rpbh[t] = rpb_table[t * NH_ + head];

    int widx = win & 511;
    int tb = widx >> 6, hb = (widx >> 3) & 7, wb = widx & 7;
    int ti = i >> 4, hi = (i >> 2) & 3, wi = i & 3;
    {
        int gt = tb * 8 + ti, gh = hb * 4 + hi, gw = wb * 4 + wi;
        int rt = (gt < 56) ? 0 : (gt < 60 ? 1 : 2);
        int rh = (gh < 28) ? 0 : (gh < 30 ? 1 : 2);
        int rw = (gw < 28) ? 0 : (gw < 30 ? 1 : 2);
        labels[i] = rt * 9 + rh * 3 + rw;
    }
    __syncthreads();

    // q row (fp16, raw; SCALE applied post-accumulation)
    __half2 q2[16];
    {
        const __half* qp = wbase + (size_t)i * C3;
        *(uint4*)&q2[0]  = *(const uint4*)(qp);
        *(uint4*)&q2[4]  = *(const uint4*)(qp + 8);
        *(uint4*)&q2[8]  = *(const uint4*)(qp + 16);
        *(uint4*)&q2[12] = *(const uint4*)(qp + 24);
    }
    int li  = labels[i];
    int dti = ti + 7, dhi = hi + 3, dwi = wi + 3;

    float m = -1e30f, sum = 0.f;
    float acc[32] = {};
    const __half2 hz = __float2half2_rn(0.f);
    for (int cch = 0; cch < 16; cch++) {
        float sc[8];
        float cmax = -1e30f;
        #pragma unroll
        for (int jj = 0; jj < 8; jj++) {
            int j = cch * 8 + jj;
            const __half2* k2 = (const __half2*)&khalf[j * 32];
            __half2 a0 = hz, a1 = hz, a2 = hz, a3 = hz;
            #pragma unroll
            for (int d = 0; d < 16; d += 4) {
                a0 = __hfma2(q2[d],     k2[d],     a0);
                a1 = __hfma2(q2[d + 1], k2[d + 1], a1);
                a2 = __hfma2(q2[d + 2], k2[d + 2], a2);
                a3 = __hfma2(q2[d + 3], k2[d + 3], a3);
            }
            __half2 t = __hadd2(__hadd2(a0, a1), __hadd2(a2, a3));
            float s = (__low2float(t) + __high2float(t)) * SCALE_;
            int tj = j >> 4, hj = (j >> 2) & 3, wj = j & 3;
            int idx = (dti - tj) * 15 + (dhi - hj) * 7 + (dwi - wj);
            s += rpbh[idx];
            if (labels[j] != li) s -= 100.0f;
            sc[jj] = s;
            cmax = fmaxf(cmax, s);
        }
        float newm = fmaxf(m, cmax);
        float corr = __expf(m - newm);
        sum *= corr;
        #pragma unroll
        for (int d = 0; d < 32; d++) acc[d] *= corr;
        #pragma unroll
        for (int jj = 0; jj < 8; jj++) {
            int j = cch * 8 + jj;
            float p = __expf(sc[jj] - newm);
            sum += p;
            #pragma unroll
            for (int d = 0; d < 32; d += 4) {
                float4 vv = *(const float4*)&vbuf[j * 32 + d];
                acc[d]   += p * vv.x; acc[d+1] += p * vv.y;
                acc[d+2] += p * vv.z; acc[d+3] += p * vv.w;
            }
        }
        m = newm;
    }
    float inv = 1.0f / sum;
    size_t ob = (size_t)(win * NTOK + i) * C_ + head * HD_;
    #pragma unroll
    for (int d = 0; d < 32; d += 2) {
        float a = acc[d] * inv, b = acc[d+1] * inv;
        __half ah2, al2, bh2, bl2;
        split_f16(a, ah2, al2); split_f16(b, bh2, bl2);
        *(__half2*)&ohi[ob + d] = __halves2half2(ah2, bh2);
        *(__half2*)&olo[ob + d] = __halves2half2(al2, bl2);
    }
}

// ---------------- launch ----------------
extern "C" void kernel_launch(void* const* d_in, const int* in_sizes, int n_in,
                              void* d_out, int out_size) {
    const float* x      = (const float*)d_in[0];
    const float* n1g    = (const float*)d_in[1];
    const float* n1b    = (const float*)d_in[2];
    const float* qkv_w  = (const float*)d_in[3];
    const float* qkv_b  = (const float*)d_in[4];
    const float* rpb    = (const float*)d_in[5];
    const float* proj_w = (const float*)d_in[6];
    const float* proj_b = (const float*)d_in[7];
    const float* n2g    = (const float*)d_in[8];
    const float* n2b    = (const float*)d_in[9];
    const float* fc1_w  = (const float*)d_in[10];
    const float* fc1_b  = (const float*)d_in[11];
    const float* fc2_w  = (const float*)d_in[12];
    const float* fc2_b  = (const float*)d_in[13];
    float* out = (float*)d_out;

    __half *acthi, *actlo, *hidhi, *hidlo, *w, *qkvh;
    float *x2;
    cudaGetSymbolAddress((void**)&acthi, g_act_hi);
    cudaGetSymbolAddress((void**)&actlo, g_act_lo);
    cudaGetSymbolAddress((void**)&hidhi, g_hid_hi);
    cudaGetSymbolAddress((void**)&hidlo, g_hid_lo);
    cudaGetSymbolAddress((void**)&w,     g_w);
    cudaGetSymbolAddress((void**)&qkvh,  g_qkvh);
    cudaGetSymbolAddress((void**)&x2,    g_x2);

    const int OQKV = 0, OPROJ = 110592, OFC1 = 147456, OFC2 = 294912;

    k_wconv_all<<<(442368 + 255)/256, 256>>>(qkv_w, proj_w, fc1_w, fc2_w, w);

    // 1) LN1 + shift + partition -> act hi/lo (window rows, C)
    k_ln<true><<<ROWS, 192>>>(x, n1g, n1b, acthi, actlo);

    // 2) QKV GEMM -> g_qkvh fp16
    { dim3 g(C3/96, ROWS/128); k_mma_gemm<0><<<g, 256>>>(acthi, actlo, w + OQKV, qkv_b, 192, C3, nullptr, qkvh, nullptr, nullptr); }

    // 3) windowed attention -> act hi/lo
    k_attn<<<BATCH * NWIN * NH_, NTOK>>>(qkvh, rpb, acthi, actlo);

    // 4) proj GEMM + reverse + roll + residual -> x2 fp32
    { dim3 g(C_/96, ROWS/128); k_mma_gemm<1><<<g, 256>>>(acthi, actlo, w + OPROJ, proj_b, 192, C_, x2, nullptr, nullptr, x); }

    // 5) LN2 -> act hi/lo
    k_ln<false><<<ROWS, 192>>>(x2, n2g, n2b, acthi, actlo);

    // 6) fc1 GEMM + GELU -> hidden hi/lo
    { dim3 g(CM_/96, ROWS/128); k_mma_gemm<2><<<g, 256>>>(acthi, actlo, w + OFC1, fc1_b, 192, CM_, nullptr, hidhi, hidlo, nullptr); }

    // 7) fc2 GEMM + residual -> d_out
    { dim3 g(C_/96, ROWS/128); k_mma_gemm<3><<<g, 256>>>(hidhi, hidlo, w + OFC2, fc2_b, 768, C_, out, nullptr, nullptr, x2); }
}

// round 11
// speedup vs baseline: 2.7725x; 1.3632x over previous
#include <cuda_runtime.h>
#include <cuda_fp16.h>
#include <math.h>
#include <stdint.h>

// ---------------- problem constants ----------------
#define BATCH 2
#define T_    64
#define H_    32
#define W_    32
#define C_    192
#define L_    (T_*H_*W_)
#define ROWS  (BATCH*L_)        // 131072 rows
#define NH_   6
#define HD_   32
#define NTOK  128
#define NWIN  512
#define C3    576
#define CM_   768
#define SCALE_ 0.17677669529663687f

// ---------------- scratch ----------------
__device__ __half g_act_hi[(size_t)ROWS * C_];
__device__ __half g_act_lo[(size_t)ROWS * C_];
__device__ __half g_hid_hi[(size_t)ROWS * CM_];
__device__ __half g_qkvh [(size_t)ROWS * C3];
__device__ float  g_x2   [(size_t)ROWS * C_];
__device__ __half g_w    [442368];

// ---------------- helpers ----------------
__device__ __forceinline__ uint32_t smem_u32(const void* p) {
    uint32_t a;
    asm("{ .reg .u64 t; cvta.to.shared.u64 t, %1; cvt.u32.u64 %0, t; }" : "=r"(a) : "l"(p));
    return a;
}
#define CPA16(dst, src) asm volatile("cp.async.cg.shared.global [%0], [%1], 16;" :: "r"(dst), "l"(src))
#define CPA_COMMIT()    asm volatile("cp.async.commit_group;" ::: "memory")
#define CPA_WAIT0()     asm volatile("cp.async.wait_group 0;" ::: "memory")
#define LDM4(d0,d1,d2,d3,addr) \
    asm volatile("ldmatrix.sync.aligned.m8n8.x4.shared.b16 {%0,%1,%2,%3}, [%4];" \
        : "=r"(d0), "=r"(d1), "=r"(d2), "=r"(d3) : "r"(addr))
#define LDM4T(d0,d1,d2,d3,addr) \
    asm volatile("ldmatrix.sync.aligned.m8n8.x4.trans.shared.b16 {%0,%1,%2,%3}, [%4];" \
        : "=r"(d0), "=r"(d1), "=r"(d2), "=r"(d3) : "r"(addr))

__device__ __forceinline__ void mma_f16(float* c, const uint32_t* a, const uint32_t* b) {
    asm volatile("mma.sync.aligned.m16n8k16.row.col.f32.f16.f16.f32 "
        "{%0,%1,%2,%3},{%4,%5,%6,%7},{%8,%9},{%0,%1,%2,%3};"
        : "+f"(c[0]), "+f"(c[1]), "+f"(c[2]), "+f"(c[3])
        : "r"(a[0]), "r"(a[1]), "r"(a[2]), "r"(a[3]), "r"(b[0]), "r"(b[1]));
}

__device__ __forceinline__ size_t shifted_pos(int row) {
    int win = row >> 7, n = row & 127;
    int b  = win >> 9, widx = win & 511;
    int tb = widx >> 6, hb = (widx >> 3) & 7, wb = widx & 7;
    int ti = n >> 4,   hi = (n >> 2) & 3,    wi = n & 3;
    int t  = (tb*8 + ti + 4) & 63;
    int hh = (hb*4 + hi + 2) & 31;
    int ww = (wb*4 + wi + 2) & 31;
    return (size_t)b * L_ + (size_t)t * (H_*W_) + hh * W_ + ww;
}

__device__ __forceinline__ void split_f16(float v, __half& h, __half& l) {
    h = __float2half_rn(v);
    l = __float2half_rn(v - __half2float(h));
}

// ---------------- weight convert+transpose (all 4 weights) ----------------
__global__ void k_wconv_all(const float* __restrict__ qkv_w, const float* __restrict__ proj_w,
                            const float* __restrict__ fc1_w, const float* __restrict__ fc2_w,
                            __half* __restrict__ w) {
    int idx = blockIdx.x * 256 + threadIdx.x;
    if (idx >= 442368) return;
    const float* W; int K, N, off;
    if (idx < 110592)      { W = qkv_w;  K = 192; N = 576; off = 0; }
    else if (idx < 147456) { W = proj_w; K = 192; N = 192; off = 110592; }
    else if (idx < 294912) { W = fc1_w;  K = 192; N = 768; off = 147456; }
    else                   { W = fc2_w;  K = 768; N = 192; off = 294912; }
    int u = idx - off;
    int n = u / K, k = u - n * K;
    w[idx] = __float2half_rn(W[(size_t)k * N + n]);
}

// ---------------- layernorm -> fp16 hi/lo ----------------
template<bool SHIFTMAP>
__global__ void k_ln(const float* __restrict__ x, const float* __restrict__ g,
                     const float* __restrict__ bt,
                     __half* __restrict__ ohi, __half* __restrict__ olo) {
    int r = blockIdx.x;
    int c = threadIdx.x;
    size_t src = SHIFTMAP ? shifted_pos(r) * C_ : (size_t)r * C_;
    float v = x[src + c];
    float s1 = v, s2 = v * v;
    #pragma unroll
    for (int off = 16; off; off >>= 1) {
        s1 += __shfl_down_sync(0xffffffffu, s1, off);
        s2 += __shfl_down_sync(0xffffffffu, s2, off);
    }
    __shared__ float red[12];
    int warp = c >> 5, lane = c & 31;
    if (lane == 0) { red[warp] = s1; red[6 + warp] = s2; }
    __syncthreads();
    if (c == 0) {
        float a = 0.f, bb = 0.f;
        #pragma unroll
        for (int w2 = 0; w2 < 6; w2++) { a += red[w2]; bb += red[6 + w2]; }
        red[0] = a; red[6] = bb;
    }
    __syncthreads();
    float mu   = red[0] * (1.0f / 192.0f);
    float var  = red[6] * (1.0f / 192.0f) - mu * mu;
    float rstd = rsqrtf(var + 1e-5f);
    float y = (v - mu) * rstd * g[c] + bt[c];
    __half h, l; split_f16(y, h, l);
    ohi[(size_t)r * C_ + c] = h;
    olo[(size_t)r * C_ + c] = l;
}

// ---------------- HMMA GEMM: CTA 128x96, 8 warps, k-step 16 ----------------
// SPLITA: A split hi/lo fp16 (2 MMA products); else single fp16 A.
// MODE 0: oh16 = half(A*B + bias)               (qkv -> fp16)
// MODE 1: outf[pos] = res[pos] + A*B + bias     (proj + reverse + roll + residual)
// MODE 2: ohi = half(gelu(A*B + bias))          (fc1, single fp16 out)
// MODE 3: outf = res + A*B + bias               (fc2 + residual)
#define ASTRIDE 48
template<int MODE, bool SPLITA>
__global__ __launch_bounds__(256, 2) void k_mma_gemm(
    const __half* __restrict__ Ahi, const __half* __restrict__ Alo,
    const __half* __restrict__ Bw,
    const float* __restrict__ bias, int K, int Ntot,
    float* __restrict__ outf,
    __half* __restrict__ ohi, __half* __restrict__ olo,
    const float* __restrict__ res)
{
    __shared__ __align__(16) uint8_t sAh[2 * 128 * ASTRIDE];
    __shared__ __align__(16) uint8_t sAl[2 * 128 * ASTRIDE];
    __shared__ __align__(16) uint8_t sBh[2 * 96 * ASTRIDE];

    const int tid = threadIdx.x;
    const int wid = tid >> 5, lane = tid & 31;
    const int wm = wid & 3, wn = wid >> 2;
    const int bm = blockIdx.y * 128;
    const int bn = blockIdx.x * 96;
    const uint32_t aH = smem_u32(sAh), aL = smem_u32(sAl);
    const uint32_t bH = smem_u32(sBh);
    const int NC = K >> 4;

    float acc[2][6][4];
    #pragma unroll
    for (int i = 0; i < 2; i++)
        #pragma unroll
        for (int j = 0; j < 6; j++)
            #pragma unroll
            for (int q = 0; q < 4; q++) acc[i][j][q] = 0.f;

    auto load_stage = [&](int c, int s) {
        const int k0 = c << 4;
        {
            int r = tid & 127, ch = (tid >> 7) & 1;
            uint32_t d = (uint32_t)(s * 128 * ASTRIDE + r * ASTRIDE + ch * 16);
            CPA16(aH + d, Ahi + (size_t)(bm + r) * K + k0 + ch * 8);
            if (SPLITA) CPA16(aL + d, Alo + (size_t)(bm + r) * K + k0 + ch * 8);
        }
        if (tid < 192) {
            int r = tid >> 1, ch = tid & 1;
            uint32_t d = (uint32_t)(s * 96 * ASTRIDE + r * ASTRIDE + ch * 16);
            CPA16(bH + d, Bw + (size_t)(bn + r) * K + k0 + ch * 8);
        }
        CPA_COMMIT();
    };

    load_stage(0, 0);

    const int arow = wm * 32 + (lane & 15);
    const uint32_t aoff = ((uint32_t)lane >> 4) * 16;
    const int g = lane >> 3;
    const int brow = wn * 48 + ((g >> 1) << 3) + (lane & 7);
    const uint32_t boff = (uint32_t)(g & 1) * 16;

    for (int c = 0; c < NC; c++) {
        const int s = c & 1;
        CPA_WAIT0();
        __syncthreads();
        if (c + 1 < NC) load_stage(c + 1, s ^ 1);

        uint32_t ah[2][4], al[2][4], bh[3][4];
        #pragma unroll
        for (int mt = 0; mt < 2; mt++) {
            uint32_t ad = (uint32_t)(s * 128 * ASTRIDE + (arow + mt * 16) * ASTRIDE) + aoff;
            LDM4(ah[mt][0], ah[mt][1], ah[mt][2], ah[mt][3], aH + ad);
            if (SPLITA) LDM4(al[mt][0], al[mt][1], al[mt][2], al[mt][3], aL + ad);
        }
        #pragma unroll
        for (int p = 0; p < 3; p++) {
            uint32_t bd = (uint32_t)(s * 96 * ASTRIDE + (brow + p * 16) * ASTRIDE) + boff;
            LDM4(bh[p][0], bh[p][1], bh[p][2], bh[p][3], bH + bd);
        }
        #pragma unroll
        for (int mt = 0; mt < 2; mt++)
            #pragma unroll
            for (int p = 0; p < 3; p++)
                #pragma unroll
                for (int q = 0; q < 2; q++) {
                    float* d = acc[mt][p * 2 + q];
                    mma_f16(d, ah[mt], &bh[p][q * 2]);
                    if (SPLITA) mma_f16(d, al[mt], &bh[p][q * 2]);
                }
        __syncthreads();
    }

    // ---- epilogue ----
    const float* biasp = bias + bn;
    #pragma unroll
    for (int mt = 0; mt < 2; mt++) {
        #pragma unroll
        for (int ro = 0; ro < 2; ro++) {
            int grow = bm + wm * 32 + mt * 16 + (lane >> 2) + ro * 8;
            size_t dstbase;
            if (MODE == 1)      dstbase = shifted_pos(grow) * (size_t)192;
            else if (MODE == 2) dstbase = (size_t)grow * CM_;
            else                dstbase = (size_t)grow * Ntot;
            #pragma unroll
            for (int nt = 0; nt < 6; nt++) {
                int col = wn * 48 + nt * 8 + (lane & 3) * 2;
                float v0 = acc[mt][nt][ro * 2 + 0] + __ldg(biasp + col);
                float v1 = acc[mt][nt][ro * 2 + 1] + __ldg(biasp + col + 1);
                size_t oi = dstbase + bn + col;
                if (MODE == 0) {
                    *(__half2*)&ohi[oi] = __halves2half2(__float2half_rn(v0), __float2half_rn(v1));
                } else if (MODE == 2) {
                    v0 = 0.5f * v0 * (1.0f + erff(v0 * 0.70710678118654752f));
                    v1 = 0.5f * v1 * (1.0f + erff(v1 * 0.70710678118654752f));
                    *(__half2*)&ohi[oi] = __halves2half2(__float2half_rn(v0), __float2half_rn(v1));
                } else {
                    float2 rv = *(const float2*)&res[oi];
                    float2 v; v.x = rv.x + v0; v.y = rv.y + v1;
                    *(float2*)&outf[oi] = v;
                }
            }
        }
    }
}

// ---------------- MMA flash attention: one block per (window, head), 4 warps ----------------
// Q/K/V staged in smem (stride 40 halves, conflict-free ldmatrix).
// Per warp: 32 query rows. Streaming softmax over 4 key-blocks of 32.
__global__ __launch_bounds__(128) void k_attn(const __half* __restrict__ qkvh,
                       const float* __restrict__ rpb_table,
                       __half* __restrict__ ohi, __half* __restrict__ olo) {
    __shared__ __align__(16) __half Qs[128 * 40];
    __shared__ __align__(16) __half Ks[128 * 40];
    __shared__ __align__(16) __half Vs[128 * 40];
    __shared__ float rpbh[736];
    __shared__ int   cjl[128];

    const int blk = blockIdx.x;
    const int win = blk / NH_, head = blk % NH_;
    const int tid = threadIdx.x;
    const int w = tid >> 5, lane = tid & 31;
    const __half* wbase = qkvh + (size_t)win * NTOK * C3 + head * HD_;

    // stage Q/K/V rows (4 threads x uint4 per row)
    {
        int r = tid >> 2, cc = (tid & 3) * 8;
        for (int rr = r; rr < 128; rr += 32) {
            const __half* p = wbase + (size_t)rr * C3;
            *(uint4*)&Qs[rr * 40 + cc] = *(const uint4*)(p + cc);
            *(uint4*)&Ks[rr * 40 + cc] = *(const uint4*)(p + 192 + cc);
            *(uint4*)&Vs[rr * 40 + cc] = *(const uint4*)(p + 384 + cc);
        }
    }
    for (int t = tid; t < 735; t += 128) rpbh[t] = rpb_table[t * NH_ + head];
    const int widx = win & 511;
    {
        int j = tid;
        int tj = j >> 4, hj = (j >> 2) & 3, wj = j & 3;
        int tb = widx >> 6, hb = (widx >> 3) & 7, wb = widx & 7;
        int gt = tb * 8 + tj, gh = hb * 4 + hj, gw = wb * 4 + wj;
        int rt = (gt < 56) ? 0 : (gt < 60 ? 1 : 2);
        int rh = (gh < 28) ? 0 : (gh < 30 ? 1 : 2);
        int rw = (gw < 28) ? 0 : (gw < 30 ? 1 : 2);
        cjl[j] = ((tj * 15 + hj * 7 + wj) << 5) | (rt * 9 + rh * 3 + rw);
    }
    __syncthreads();

    const bool uni = ((widx >> 6) < 7) && (((widx >> 3) & 7) < 7) && ((widx & 7) < 7);

    // per-thread row constants (4 rows: mt*16 + hc*8 + lane>>2)
    int ibase[4], ilab[4];
    #pragma unroll
    for (int rr = 0; rr < 4; rr++) {
        int i = w * 32 + (rr >> 1) * 16 + (rr & 1) * 8 + (lane >> 2);
        int v = cjl[i];
        ibase[rr] = (v >> 5) + 129;   // (7,3,3) offset: 7*15+3*7+3
        ilab[rr]  = v & 31;
    }

    // Q A-fragments: aq[kt(d16)][mt][4]
    uint32_t aq[2][2][4];
    #pragma unroll
    for (int kt = 0; kt < 2; kt++)
        #pragma unroll
        for (int mt = 0; mt < 2; mt++) {
            uint32_t ad = smem_u32(&Qs[(w * 32 + mt * 16 + (lane & 15)) * 40 + kt * 16 + 8 * (lane >> 4)]);
            LDM4(aq[kt][mt][0], aq[kt][mt][1], aq[kt][mt][2], aq[kt][mt][3], ad);
        }

    float m[4] = {-1e30f, -1e30f, -1e30f, -1e30f};
    float sum[4] = {};
    float acc2[2][4][4] = {};

    for (int kb = 0; kb < 4; kb++) {
        // K B-fragments: bk[jn][4] covers d=0..31 for keys jn*8..+7
        uint32_t bk[4][4];
        #pragma unroll
        for (int jn = 0; jn < 4; jn++) {
            uint32_t ad = smem_u32(&Ks[(kb * 32 + jn * 8 + (lane & 7)) * 40 + 8 * (lane >> 3)]);
            LDM4(bk[jn][0], bk[jn][1], bk[jn][2], bk[jn][3], ad);
        }
        // S = Q K^T (fp32 accum)
        float sc[2][4][4] = {};
        #pragma unroll
        for (int mt = 0; mt < 2; mt++)
            #pragma unroll
            for (int jn = 0; jn < 4; jn++) {
                mma_f16(sc[mt][jn], aq[0][mt], &bk[jn][0]);
                mma_f16(sc[mt][jn], aq[1][mt], &bk[jn][2]);
            }
        // scale + rpb + mask
        int jb = kb * 32 + (lane & 3) * 2;
        #pragma unroll
        for (int jn = 0; jn < 4; jn++) {
            int v0 = cjl[jb + jn * 8];
            int v1 = cjl[jb + jn * 8 + 1];
            #pragma unroll
            for (int mt = 0; mt < 2; mt++)
                #pragma unroll
                for (int c = 0; c < 4; c++) {
                    int vv = (c & 1) ? v1 : v0;
                    int rr = mt * 2 + (c >> 1);
                    float s = sc[mt][jn][c] * SCALE_ + rpbh[ibase[rr] - (vv >> 5)];
                    if (!uni && ilab[rr] != (vv & 31)) s -= 100.0f;
                    sc[mt][jn][c] = s;
                }
        }
        // row max (quad reduce)
        float rmax[4] = {-1e30f, -1e30f, -1e30f, -1e30f};
        #pragma unroll
        for (int mt = 0; mt < 2; mt++)
            #pragma unroll
            for (int jn = 0; jn < 4; jn++)
                #pragma unroll
                for (int c = 0; c < 4; c++)
                    rmax[mt * 2 + (c >> 1)] = fmaxf(rmax[mt * 2 + (c >> 1)], sc[mt][jn][c]);
        #pragma unroll
        for (int rr = 0; rr < 4; rr++) {
            rmax[rr] = fmaxf(rmax[rr], __shfl_xor_sync(0xffffffffu, rmax[rr], 1));
            rmax[rr] = fmaxf(rmax[rr], __shfl_xor_sync(0xffffffffu, rmax[rr], 2));
        }
        float corr[4];
        #pragma unroll
        for (int rr = 0; rr < 4; rr++) {
            float nm = fmaxf(m[rr], rmax[rr]);
            corr[rr] = __expf(m[rr] - nm);
            m[rr] = nm;
            sum[rr] *= corr[rr];
        }
        #pragma unroll
        for (int mt = 0; mt < 2; mt++)
            #pragma unroll
            for (int vn = 0; vn < 4; vn++)
                #pragma unroll
                for (int c = 0; c < 4; c++)
                    acc2[mt][vn][c] *= corr[mt * 2 + (c >> 1)];
        // p = exp(s - m); pack into PV A-fragments
        uint32_t ap[2][2][4];
        #pragma unroll
        for (int mt = 0; mt < 2; mt++)
            #pragma unroll
            for (int jn = 0; jn < 4; jn++) {
                float p0 = __expf(sc[mt][jn][0] - m[mt * 2]);
                float p1 = __expf(sc[mt][jn][1] - m[mt * 2]);
                float p2 = __expf(sc[mt][jn][2] - m[mt * 2 + 1]);
                float p3 = __expf(sc[mt][jn][3] - m[mt * 2 + 1]);
                sum[mt * 2]     += p0 + p1;
                sum[mt * 2 + 1] += p2 + p3;
                __half2 hA = __floats2half2_rn(p0, p1);
                __half2 hB = __floats2half2_rn(p2, p3);
                ap[jn >> 1][mt][(jn & 1) * 2]     = *(uint32_t*)&hA;
                ap[jn >> 1][mt][(jn & 1) * 2 + 1] = *(uint32_t*)&hB;
            }
        // PV: B from V via ldmatrix.trans
        #pragma unroll
        for (int vn = 0; vn < 4; vn++) {
            uint32_t bv[4];
            uint32_t ad = smem_u32(&Vs[(kb * 32 + 8 * (lane >> 3) + (lane & 7)) * 40 + vn * 8]);
            LDM4T(bv[0], bv[1], bv[2], bv[3], ad);
            #pragma unroll
            for (int mt = 0; mt < 2; mt++) {
                mma_f16(acc2[mt][vn], ap[0][mt], &bv[0]);
                mma_f16(acc2[mt][vn], ap[1][mt], &bv[2]);
            }
        }
    }
    // final sum across quad, normalize, write hi/lo
    float inv[4];
    #pragma unroll
    for (int rr = 0; rr < 4; rr++) {
        sum[rr] += __shfl_xor_sync(0xffffffffu, sum[rr], 1);
        sum[rr] += __shfl_xor_sync(0xffffffffu, sum[rr], 2);
        inv[rr] = 1.0f / sum[rr];
    }
    #pragma unroll
    for (int mt = 0; mt < 2; mt++) {
        size_t row0 = (size_t)(win * 128 + w * 32 + mt * 16 + (lane >> 2));
        #pragma unroll
        for (int vn = 0; vn < 4; vn++) {
            size_t o = row0 * C_ + head * HD_ + vn * 8 + (lane & 3) * 2;
            float v0 = acc2[mt][vn][0] * inv[mt * 2];
            float v1 = acc2[mt][vn][1] * inv[mt * 2];
            __half h0, l0, h1, l1;
            split_f16(v0, h0, l0); split_f16(v1, h1, l1);
            *(__half2*)&ohi[o] = __halves2half2(h0, h1);
            *(__half2*)&olo[o] = __halves2half2(l0, l1);
            v0 = acc2[mt][vn][2] * inv[mt * 2 + 1];
            v1 = acc2[mt][vn][3] * inv[mt * 2 + 1];
            split_f16(v0, h0, l0); split_f16(v1, h1, l1);
            size_t o2 = o + 8 * C_;
            *(__half2*)&ohi[o2] = __halves2half2(h0, h1);
            *(__half2*)&olo[o2] = __halves2half2(l0, l1);
        }
    }
}

// ---------------- launch ----------------
extern "C" void kernel_launch(void* const* d_in, const int* in_sizes, int n_in,
                              void* d_out, int out_size) {
    const float* x      = (const float*)d_in[0];
    const float* n1g    = (const float*)d_in[1];
    const float* n1b    = (const float*)d_in[2];
    const float* qkv_w  = (const float*)d_in[3];
    const float* qkv_b  = (const float*)d_in[4];
    const float* rpb    = (const float*)d_in[5];
    const float* proj_w = (const float*)d_in[6];
    const float* proj_b = (const float*)d_in[7];
    const float* n2g    = (const float*)d_in[8];
    const float* n2b    = (const float*)d_in[9];
    const float* fc1_w  = (const float*)d_in[10];
    const float* fc1_b  = (const float*)d_in[11];
    const float* fc2_w  = (const float*)d_in[12];
    const float* fc2_b  = (const float*)d_in[13];
    float* out = (float*)d_out;

    __half *acthi, *actlo, *hidhi, *w, *qkvh;
    float *x2;
    cudaGetSymbolAddress((void**)&acthi, g_act_hi);
    cudaGetSymbolAddress((void**)&actlo, g_act_lo);
    cudaGetSymbolAddress((void**)&hidhi, g_hid_hi);
    cudaGetSymbolAddress((void**)&w,     g_w);
    cudaGetSymbolAddress((void**)&qkvh,  g_qkvh);
    cudaGetSymbolAddress((void**)&x2,    g_x2);

    const int OQKV = 0, OPROJ = 110592, OFC1 = 147456, OFC2 = 294912;

    k_wconv_all<<<(442368 + 255)/256, 256>>>(qkv_w, proj_w, fc1_w, fc2_w, w);

    // 1) LN1 + shift + partition -> act hi/lo (window rows, C)
    k_ln<true><<<ROWS, 192>>>(x, n1g, n1b, acthi, actlo);

    // 2) QKV GEMM -> g_qkvh fp16
    { dim3 g(C3/96, ROWS/128); k_mma_gemm<0, true><<<g, 256>>>(acthi, actlo, w + OQKV, qkv_b, 192, C3, nullptr, qkvh, nullptr, nullptr); }

    // 3) MMA windowed attention -> act hi/lo
    k_attn<<<BATCH * NWIN * NH_, 128>>>(qkvh, rpb, acthi, actlo);

    // 4) proj GEMM + reverse + roll + residual -> x2 fp32
    { dim3 g(C_/96, ROWS/128); k_mma_gemm<1, true><<<g, 256>>>(acthi, actlo, w + OPROJ, proj_b, 192, C_, x2, nullptr, nullptr, x); }

    // 5) LN2 -> act hi/lo
    k_ln<false><<<ROWS, 192>>>(x2, n2g, n2b, acthi, actlo);

    // 6) fc1 GEMM + GELU -> hidden fp16 (single)
    { dim3 g(CM_/96, ROWS/128); k_mma_gemm<2, true><<<g, 256>>>(acthi, actlo, w + OFC1, fc1_b, 192, CM_, nullptr, hidhi, nullptr, nullptr); }

    // 7) fc2 GEMM (single-A) + residual -> d_out
    { dim3 g(C_/96, ROWS/128); k_mma_gemm<3, false><<<g, 256>>>(hidhi, nullptr, w + OFC2, fc2_b, 768, C_, out, nullptr, nullptr, x2); }
}

// round 12
// speedup vs baseline: 3.4718x; 1.2522x over previous
#include <cuda_runtime.h>
#include <cuda_fp16.h>
#include <math.h>
#include <stdint.h>

// ---------------- problem constants ----------------
#define BATCH 2
#define T_    64
#define H_    32
#define W_    32
#define C_    192
#define L_    (T_*H_*W_)
#define ROWS  (BATCH*L_)        // 131072 rows
#define NH_   6
#define HD_   32
#define NTOK  128
#define NWIN  512
#define C3    576
#define CM_   768
#define SCALE_ 0.17677669529663687f

// ---------------- scratch ----------------
__device__ __half g_act_hi[(size_t)ROWS * C_];
__device__ __half g_act_lo[(size_t)ROWS * C_];
__device__ __half g_hid_hi[(size_t)ROWS * CM_];
__device__ __half g_qkvh [(size_t)ROWS * C3];
__device__ float  g_x2   [(size_t)ROWS * C_];
__device__ __half g_w    [442368];

// ---------------- helpers ----------------
__device__ __forceinline__ uint32_t smem_u32(const void* p) {
    uint32_t a;
    asm("{ .reg .u64 t; cvta.to.shared.u64 t, %1; cvt.u32.u64 %0, t; }" : "=r"(a) : "l"(p));
    return a;
}
#define CPA16(dst, src) asm volatile("cp.async.cg.shared.global [%0], [%1], 16;" :: "r"(dst), "l"(src))
#define CPA_COMMIT()    asm volatile("cp.async.commit_group;" ::: "memory")
#define CPA_WAIT2()     asm volatile("cp.async.wait_group 2;" ::: "memory")
#define LDM4(d0,d1,d2,d3,addr) \
    asm volatile("ldmatrix.sync.aligned.m8n8.x4.shared.b16 {%0,%1,%2,%3}, [%4];" \
        : "=r"(d0), "=r"(d1), "=r"(d2), "=r"(d3) : "r"(addr))
#define LDM4T(d0,d1,d2,d3,addr) \
    asm volatile("ldmatrix.sync.aligned.m8n8.x4.trans.shared.b16 {%0,%1,%2,%3}, [%4];" \
        : "=r"(d0), "=r"(d1), "=r"(d2), "=r"(d3) : "r"(addr))

__device__ __forceinline__ void mma_f16(float* c, const uint32_t* a, const uint32_t* b) {
    asm volatile("mma.sync.aligned.m16n8k16.row.col.f32.f16.f16.f32 "
        "{%0,%1,%2,%3},{%4,%5,%6,%7},{%8,%9},{%0,%1,%2,%3};"
        : "+f"(c[0]), "+f"(c[1]), "+f"(c[2]), "+f"(c[3])
        : "r"(a[0]), "r"(a[1]), "r"(a[2]), "r"(a[3]), "r"(b[0]), "r"(b[1]));
}

__device__ __forceinline__ size_t shifted_pos(int row) {
    int win = row >> 7, n = row & 127;
    int b  = win >> 9, widx = win & 511;
    int tb = widx >> 6, hb = (widx >> 3) & 7, wb = widx & 7;
    int ti = n >> 4,   hi = (n >> 2) & 3,    wi = n & 3;
    int t  = (tb*8 + ti + 4) & 63;
    int hh = (hb*4 + hi + 2) & 31;
    int ww = (wb*4 + wi + 2) & 31;
    return (size_t)b * L_ + (size_t)t * (H_*W_) + hh * W_ + ww;
}

__device__ __forceinline__ void split_f16(float v, __half& h, __half& l) {
    h = __float2half_rn(v);
    l = __float2half_rn(v - __half2float(h));
}

// swizzled smem offset for a (row, 16B-chunk) pair, 32B logical rows, zero padding.
// conflict-free for ldmatrix: granule = row*2 + ((row>>2)&1 ^ ch), distinct mod 8 per phase.
__device__ __forceinline__ uint32_t swz(int row, int ch) {
    return (uint32_t)(row * 32 + ((((row >> 2) & 1) ^ ch) << 4));
}

// ---------------- weight convert+transpose (all 4 weights) ----------------
__global__ void k_wconv_all(const float* __restrict__ qkv_w, const float* __restrict__ proj_w,
                            const float* __restrict__ fc1_w, const float* __restrict__ fc2_w,
                            __half* __restrict__ w) {
    int idx = blockIdx.x * 256 + threadIdx.x;
    if (idx >= 442368) return;
    const float* W; int K, N, off;
    if (idx < 110592)      { W = qkv_w;  K = 192; N = 576; off = 0; }
    else if (idx < 147456) { W = proj_w; K = 192; N = 192; off = 110592; }
    else if (idx < 294912) { W = fc1_w;  K = 192; N = 768; off = 147456; }
    else                   { W = fc2_w;  K = 768; N = 192; off = 294912; }
    int u = idx - off;
    int n = u / K, k = u - n * K;
    w[idx] = __float2half_rn(W[(size_t)k * N + n]);
}

// ---------------- layernorm -> fp16 hi/lo ----------------
template<bool SHIFTMAP>
__global__ void k_ln(const float* __restrict__ x, const float* __restrict__ g,
                     const float* __restrict__ bt,
                     __half* __restrict__ ohi, __half* __restrict__ olo) {
    int r = blockIdx.x;
    int c = threadIdx.x;
    size_t src = SHIFTMAP ? shifted_pos(r) * C_ : (size_t)r * C_;
    float v = x[src + c];
    float s1 = v, s2 = v * v;
    #pragma unroll
    for (int off = 16; off; off >>= 1) {
        s1 += __shfl_down_sync(0xffffffffu, s1, off);
        s2 += __shfl_down_sync(0xffffffffu, s2, off);
    }
    __shared__ float red[12];
    int warp = c >> 5, lane = c & 31;
    if (lane == 0) { red[warp] = s1; red[6 + warp] = s2; }
    __syncthreads();
    if (c == 0) {
        float a = 0.f, bb = 0.f;
        #pragma unroll
        for (int w2 = 0; w2 < 6; w2++) { a += red[w2]; bb += red[6 + w2]; }
        red[0] = a; red[6] = bb;
    }
    __syncthreads();
    float mu   = red[0] * (1.0f / 192.0f);
    float var  = red[6] * (1.0f / 192.0f) - mu * mu;
    float rstd = rsqrtf(var + 1e-5f);
    float y = (v - mu) * rstd * g[c] + bt[c];
    __half h, l; split_f16(y, h, l);
    ohi[(size_t)r * C_ + c] = h;
    olo[(size_t)r * C_ + c] = l;
}

// ---------------- HMMA GEMM: CTA 128x96, 8 warps, k-step 16, 4-stage cp.async pipeline ----------------
// SPLITA: A split hi/lo fp16 (2 MMA products); else single fp16 A.
// MODE 0: oh16 = half(A*B + bias)               (qkv -> fp16)
// MODE 1: outf[pos] = res[pos] + A*B + bias     (proj + reverse + roll + residual)
// MODE 2: ohi = half(gelu(A*B + bias))          (fc1, single fp16 out)
// MODE 3: outf = res + A*B + bias               (fc2 + residual)
template<int MODE, bool SPLITA>
__global__ __launch_bounds__(256, 2) void k_mma_gemm(
    const __half* __restrict__ Ahi, const __half* __restrict__ Alo,
    const __half* __restrict__ Bw,
    const float* __restrict__ bias, int K, int Ntot,
    float* __restrict__ outf,
    __half* __restrict__ ohi, __half* __restrict__ olo,
    const float* __restrict__ res)
{
    // 4 stages, swizzled (no padding): A stage 4 KB, B stage 3 KB
    __shared__ __align__(16) uint8_t sAh[4 * 128 * 32];
    __shared__ __align__(16) uint8_t sAl[4 * 128 * 32];
    __shared__ __align__(16) uint8_t sBh[4 * 96 * 32];

    const int tid = threadIdx.x;
    const int wid = tid >> 5, lane = tid & 31;
    const int wm = wid & 3, wn = wid >> 2;
    const int bm = blockIdx.y * 128;
    const int bn = blockIdx.x * 96;
    const uint32_t aH = smem_u32(sAh), aL = smem_u32(sAl);
    const uint32_t bH = smem_u32(sBh);
    const int NC = K >> 4;   // >= 12 always

    float acc[2][6][4];
    #pragma unroll
    for (int i = 0; i < 2; i++)
        #pragma unroll
        for (int j = 0; j < 6; j++)
            #pragma unroll
            for (int q = 0; q < 4; q++) acc[i][j][q] = 0.f;

    // per-thread load assignment
    const int lar = tid >> 1, lach = tid & 1;           // A: 128 rows x 2 chunks
    const int lbr = (tid < 192) ? (tid >> 1) : 0;       // B: 96 rows x 2 chunks
    const uint32_t aoffA = swz(lar, lach);
    const uint32_t aoffB = swz(lbr, lach);

    auto load_stage = [&](int c) {
        const int s = c & 3;
        const int k0 = c << 4;
        {
            uint32_t d = (uint32_t)(s * 4096) + aoffA;
            const size_t gs = (size_t)(bm + lar) * K + k0 + lach * 8;
            CPA16(aH + d, Ahi + gs);
            if (SPLITA) CPA16(aL + d, Alo + gs);
        }
        if (tid < 192) {
            uint32_t d = (uint32_t)(s * 3072) + aoffB;
            CPA16(bH + d, Bw + (size_t)(bn + lbr) * K + k0 + lach * 8);
        }
        CPA_COMMIT();
    };

    load_stage(0); load_stage(1); load_stage(2);

    const int arow0 = wm * 32 + (lane & 15);
    const int ach = lane >> 4;
    const int g = lane >> 3;
    const int brow0 = wn * 48 + ((g >> 1) << 3) + (lane & 7);
    const int bch = g & 1;

    for (int c = 0; c < NC; c++) {
        const int s = c & 3;
        CPA_WAIT2();
        __syncthreads();
        if (c + 3 < NC) load_stage(c + 3);
        else            CPA_COMMIT();   // empty group keeps wait-depth arithmetic valid

        uint32_t ah[2][4], al[2][4], bh[3][4];
        #pragma unroll
        for (int mt = 0; mt < 2; mt++) {
            int row = arow0 + mt * 16;
            uint32_t ad = (uint32_t)(s * 4096) + swz(row, ach);
            LDM4(ah[mt][0], ah[mt][1], ah[mt][2], ah[mt][3], aH + ad);
            if (SPLITA) LDM4(al[mt][0], al[mt][1], al[mt][2], al[mt][3], aL + ad);
        }
        #pragma unroll
        for (int p = 0; p < 3; p++) {
            int row = brow0 + p * 16;
            uint32_t bd = (uint32_t)(s * 3072) + swz(row, bch);
            LDM4(bh[p][0], bh[p][1], bh[p][2], bh[p][3], bH + bd);
        }
        #pragma unroll
        for (int mt = 0; mt < 2; mt++)
            #pragma unroll
            for (int p = 0; p < 3; p++)
                #pragma unroll
                for (int q = 0; q < 2; q++) {
                    float* d = acc[mt][p * 2 + q];
                    mma_f16(d, ah[mt], &bh[p][q * 2]);
                    if (SPLITA) mma_f16(d, al[mt], &bh[p][q * 2]);
                }
    }

    // ---- epilogue ----
    const float* biasp = bias + bn;
    #pragma unroll
    for (int mt = 0; mt < 2; mt++) {
        #pragma unroll
        for (int ro = 0; ro < 2; ro++) {
            int grow = bm + wm * 32 + mt * 16 + (lane >> 2) + ro * 8;
            size_t dstbase;
            if (MODE == 1)      dstbase = shifted_pos(grow) * (size_t)192;
            else if (MODE == 2) dstbase = (size_t)grow * CM_;
            else                dstbase = (size_t)grow * Ntot;
            #pragma unroll
            for (int nt = 0; nt < 6; nt++) {
                int col = wn * 48 + nt * 8 + (lane & 3) * 2;
                float v0 = acc[mt][nt][ro * 2 + 0] + __ldg(biasp + col);
                float v1 = acc[mt][nt][ro * 2 + 1] + __ldg(biasp + col + 1);
                size_t oi = dstbase + bn + col;
                if (MODE == 0) {
                    *(__half2*)&ohi[oi] = __halves2half2(__float2half_rn(v0), __float2half_rn(v1));
                } else if (MODE == 2) {
                    v0 = 0.5f * v0 * (1.0f + erff(v0 * 0.70710678118654752f));
                    v1 = 0.5f * v1 * (1.0f + erff(v1 * 0.70710678118654752f));
                    *(__half2*)&ohi[oi] = __halves2half2(__float2half_rn(v0), __float2half_rn(v1));
                } else {
                    float2 rv = *(const float2*)&res[oi];
                    float2 v; v.x = rv.x + v0; v.y = rv.y + v1;
                    *(float2*)&outf[oi] = v;
                }
            }
        }
    }
}

// ---------------- MMA flash attention: one block per (window, head), 4 warps ----------------
__global__ __launch_bounds__(128) void k_attn(const __half* __restrict__ qkvh,
                       const float* __restrict__ rpb_table,
                       __half* __restrict__ ohi, __half* __restrict__ olo) {
    __shared__ __align__(16) __half Qs[128 * 40];
    __shared__ __align__(16) __half Ks[128 * 40];
    __shared__ __align__(16) __half Vs[128 * 40];
    __shared__ float rpbh[736];
    __shared__ int   cjl[128];

    const int blk = blockIdx.x;
    const int win = blk / NH_, head = blk % NH_;
    const int tid = threadIdx.x;
    const int w = tid >> 5, lane = tid & 31;
    const __half* wbase = qkvh + (size_t)win * NTOK * C3 + head * HD_;

    {
        int r = tid >> 2, cc = (tid & 3) * 8;
        for (int rr = r; rr < 128; rr += 32) {
            const __half* p = wbase + (size_t)rr * C3;
            *(uint4*)&Qs[rr * 40 + cc] = *(const uint4*)(p + cc);
            *(uint4*)&Ks[rr * 40 + cc] = *(const uint4*)(p + 192 + cc);
            *(uint4*)&Vs[rr * 40 + cc] = *(const uint4*)(p + 384 + cc);
        }
    }
    for (int t = tid; t < 735; t += 128) rpbh[t] = rpb_table[t * NH_ + head];
    const int widx = win & 511;
    {
        int j = tid;
        int tj = j >> 4, hj = (j >> 2) & 3, wj = j & 3;
        int tb = widx >> 6, hb = (widx >> 3) & 7, wb = widx & 7;
        int gt = tb * 8 + tj, gh = hb * 4 + hj, gw = wb * 4 + wj;
        int rt = (gt < 56) ? 0 : (gt < 60 ? 1 : 2);
        int rh = (gh < 28) ? 0 : (gh < 30 ? 1 : 2);
        int rw = (gw < 28) ? 0 : (gw < 30 ? 1 : 2);
        cjl[j] = ((tj * 15 + hj * 7 + wj) << 5) | (rt * 9 + rh * 3 + rw);
    }
    __syncthreads();

    const bool uni = ((widx >> 6) < 7) && (((widx >> 3) & 7) < 7) && ((widx & 7) < 7);

    int ibase[4], ilab[4];
    #pragma unroll
    for (int rr = 0; rr < 4; rr++) {
        int i = w * 32 + (rr >> 1) * 16 + (rr & 1) * 8 + (lane >> 2);
        int v = cjl[i];
        ibase[rr] = (v >> 5) + 129;
        ilab[rr]  = v & 31;
    }

    uint32_t aq[2][2][4];
    #pragma unroll
    for (int kt = 0; kt < 2; kt++)
        #pragma unroll
        for (int mt = 0; mt < 2; mt++) {
            uint32_t ad = smem_u32(&Qs[(w * 32 + mt * 16 + (lane & 15)) * 40 + kt * 16 + 8 * (lane >> 4)]);
            LDM4(aq[kt][mt][0], aq[kt][mt][1], aq[kt][mt][2], aq[kt][mt][3], ad);
        }

    float m[4] = {-1e30f, -1e30f, -1e30f, -1e30f};
    float sum[4] = {};
    float acc2[2][4][4] = {};

    for (int kb = 0; kb < 4; kb++) {
        uint32_t bk[4][4];
        #pragma unroll
        for (int jn = 0; jn < 4; jn++) {
            uint32_t ad = smem_u32(&Ks[(kb * 32 + jn * 8 + (lane & 7)) * 40 + 8 * (lane >> 3)]);
            LDM4(bk[jn][0], bk[jn][1], bk[jn][2], bk[jn][3], ad);
        }
        float sc[2][4][4] = {};
        #pragma unroll
        for (int mt = 0; mt < 2; mt++)
            #pragma unroll
            for (int jn = 0; jn < 4; jn++) {
                mma_f16(sc[mt][jn], aq[0][mt], &bk[jn][0]);
                mma_f16(sc[mt][jn], aq[1][mt], &bk[jn][2]);
            }
        int jb = kb * 32 + (lane & 3) * 2;
        #pragma unroll
        for (int jn = 0; jn < 4; jn++) {
            int v0 = cjl[jb + jn * 8];
            int v1 = cjl[jb + jn * 8 + 1];
            #pragma unroll
            for (int mt = 0; mt < 2; mt++)
                #pragma unroll
                for (int c = 0; c < 4; c++) {
                    int vv = (c & 1) ? v1 : v0;
                    int rr = mt * 2 + (c >> 1);
                    float s = sc[mt][jn][c] * SCALE_ + rpbh[ibase[rr] - (vv >> 5)];
                    if (!uni && ilab[rr] != (vv & 31)) s -= 100.0f;
                    sc[mt][jn][c] = s;
                }
        }
        float rmax[4] = {-1e30f, -1e30f, -1e30f, -1e30f};
        #pragma unroll
        for (int mt = 0; mt < 2; mt++)
            #pragma unroll
            for (int jn = 0; jn < 4; jn++)
                #pragma unroll
                for (int c = 0; c < 4; c++)
                    rmax[mt * 2 + (c >> 1)] = fmaxf(rmax[mt * 2 + (c >> 1)], sc[mt][jn][c]);
        #pragma unroll
        for (int rr = 0; rr < 4; rr++) {
            rmax[rr] = fmaxf(rmax[rr], __shfl_xor_sync(0xffffffffu, rmax[rr], 1));
            rmax[rr] = fmaxf(rmax[rr], __shfl_xor_sync(0xffffffffu, rmax[rr], 2));
        }
        float corr[4];
        #pragma unroll
        for (int rr = 0; rr < 4; rr++) {
            float nm = fmaxf(m[rr], rmax[rr]);
            corr[rr] = __expf(m[rr] - nm);
            m[rr] = nm;
            sum[rr] *= corr[rr];
        }
        #pragma unroll
        for (int mt = 0; mt < 2; mt++)
            #pragma unroll
            for (int vn = 0; vn < 4; vn++)
                #pragma unroll
                for (int c = 0; c < 4; c++)
                    acc2[mt][vn][c] *= corr[mt * 2 + (c >> 1)];
        uint32_t ap[2][2][4];
        #pragma unroll
        for (int mt = 0; mt < 2; mt++)
            #pragma unroll
            for (int jn = 0; jn < 4; jn++) {
                float p0 = __expf(sc[mt][jn][0] - m[mt * 2]);
                float p1 = __expf(sc[mt][jn][1] - m[mt * 2]);
                float p2 = __expf(sc[mt][jn][2] - m[mt * 2 + 1]);
                float p3 = __expf(sc[mt][jn][3] - m[mt * 2 + 1]);
                sum[mt * 2]     += p0 + p1;
                sum[mt * 2 + 1] += p2 + p3;
                __half2 hA = __floats2half2_rn(p0, p1);
                __half2 hB = __floats2half2_rn(p2, p3);
                ap[jn >> 1][mt][(jn & 1) * 2]     = *(uint32_t*)&hA;
                ap[jn >> 1][mt][(jn & 1) * 2 + 1] = *(uint32_t*)&hB;
            }
        #pragma unroll
        for (int vn = 0; vn < 4; vn++) {
            uint32_t bv[4];
            uint32_t ad = smem_u32(&Vs[(kb * 32 + 8 * (lane >> 3) + (lane & 7)) * 40 + vn * 8]);
            LDM4T(bv[0], bv[1], bv[2], bv[3], ad);
            #pragma unroll
            for (int mt = 0; mt < 2; mt++) {
                mma_f16(acc2[mt][vn], ap[0][mt], &bv[0]);
                mma_f16(acc2[mt][vn], ap[1][mt], &bv[2]);
            }
        }
    }
    float inv[4];
    #pragma unroll
    for (int rr = 0; rr < 4; rr++) {
        sum[rr] += __shfl_xor_sync(0xffffffffu, sum[rr], 1);
        sum[rr] += __shfl_xor_sync(0xffffffffu, sum[rr], 2);
        inv[rr] = 1.0f / sum[rr];
    }
    #pragma unroll
    for (int mt = 0; mt < 2; mt++) {
        size_t row0 = (size_t)(win * 128 + w * 32 + mt * 16 + (lane >> 2));
        #pragma unroll
        for (int vn = 0; vn < 4; vn++) {
            size_t o = row0 * C_ + head * HD_ + vn * 8 + (lane & 3) * 2;
            float v0 = acc2[mt][vn][0] * inv[mt * 2];
            float v1 = acc2[mt][vn][1] * inv[mt * 2];
            __half h0, l0, h1, l1;
            split_f16(v0, h0, l0); split_f16(v1, h1, l1);
            *(__half2*)&ohi[o] = __halves2half2(h0, h1);
            *(__half2*)&olo[o] = __halves2half2(l0, l1);
            v0 = acc2[mt][vn][2] * inv[mt * 2 + 1];
            v1 = acc2[mt][vn][3] * inv[mt * 2 + 1];
            split_f16(v0, h0, l0); split_f16(v1, h1, l1);
            size_t o2 = o + 8 * C_;
            *(__half2*)&ohi[o2] = __halves2half2(h0, h1);
            *(__half2*)&olo[o2] = __halves2half2(l0, l1);
        }
    }
}

// ---------------- launch ----------------
extern "C" void kernel_launch(void* const* d_in, const int* in_sizes, int n_in,
                              void* d_out, int out_size) {
    const float* x      = (const float*)d_in[0];
    const float* n1g    = (const float*)d_in[1];
    const float* n1b    = (const float*)d_in[2];
    const float* qkv_w  = (const float*)d_in[3];
    const float* qkv_b  = (const float*)d_in[4];
    const float* rpb    = (const float*)d_in[5];
    const float* proj_w = (const float*)d_in[6];
    const float* proj_b = (const float*)d_in[7];
    const float* n2g    = (const float*)d_in[8];
    const float* n2b    = (const float*)d_in[9];
    const float* fc1_w  = (const float*)d_in[10];
    const float* fc1_b  = (const float*)d_in[11];
    const float* fc2_w  = (const float*)d_in[12];
    const float* fc2_b  = (const float*)d_in[13];
    float* out = (float*)d_out;

    __half *acthi, *actlo, *hidhi, *w, *qkvh;
    float *x2;
    cudaGetSymbolAddress((void**)&acthi, g_act_hi);
    cudaGetSymbolAddress((void**)&actlo, g_act_lo);
    cudaGetSymbolAddress((void**)&hidhi, g_hid_hi);
    cudaGetSymbolAddress((void**)&w,     g_w);
    cudaGetSymbolAddress((void**)&qkvh,  g_qkvh);
    cudaGetSymbolAddress((void**)&x2,    g_x2);

    const int OQKV = 0, OPROJ = 110592, OFC1 = 147456, OFC2 = 294912;

    k_wconv_all<<<(442368 + 255)/256, 256>>>(qkv_w, proj_w, fc1_w, fc2_w, w);

    // 1) LN1 + shift + partition -> act hi/lo (window rows, C)
    k_ln<true><<<ROWS, 192>>>(x, n1g, n1b, acthi, actlo);

    // 2) QKV GEMM -> g_qkvh fp16
    { dim3 g(C3/96, ROWS/128); k_mma_gemm<0, true><<<g, 256>>>(acthi, actlo, w + OQKV, qkv_b, 192, C3, nullptr, qkvh, nullptr, nullptr); }

    // 3) MMA windowed attention -> act hi/lo
    k_attn<<<BATCH * NWIN * NH_, 128>>>(qkvh, rpb, acthi, actlo);

    // 4) proj GEMM + reverse + roll + residual -> x2 fp32
    { dim3 g(C_/96, ROWS/128); k_mma_gemm<1, true><<<g, 256>>>(acthi, actlo, w + OPROJ, proj_b, 192, C_, x2, nullptr, nullptr, x); }

    // 5) LN2 -> act hi/lo
    k_ln<false><<<ROWS, 192>>>(x2, n2g, n2b, acthi, actlo);

    // 6) fc1 GEMM + GELU -> hidden fp16 (single)
    { dim3 g(CM_/96, ROWS/128); k_mma_gemm<2, true><<<g, 256>>>(acthi, actlo, w + OFC1, fc1_b, 192, CM_, nullptr, hidhi, nullptr, nullptr); }

    // 7) fc2 GEMM (single-A) + residual -> d_out
    { dim3 g(C_/96, ROWS/128); k_mma_gemm<3, false><<<g, 256>>>(hidhi, nullptr, w + OFC2, fc2_b, 768, C_, out, nullptr, nullptr, x2); }
}